// round 6
// baseline (speedup 1.0000x reference)
#include <cuda_runtime.h>
#include <cuda_fp16.h>
#include <cstdint>

#define NB 512   // batch
#define DD 512   // embed dim
#define OD 512   // out dim

// -------- scratch (no cudaMalloc allowed) --------
__device__ float g_h[NB * DD];
__device__ float g_logits[NB * DD];
__device__ float g_textw[NB * DD];
__device__ float g_outx[NB * DD];
__device__ float g_gate[NB * DD];
__device__ float g_tmp[NB * DD];
__device__ __half g_WoT[OD * DD];   // WoT[o][d] = fp16(Wo[d][o])

// ============================================================
// Helpers (plain sm_80+ PTX: mma.sync / ldmatrix / cp.async)
// ============================================================
__device__ __forceinline__ uint32_t smem_u32(const void* p) {
    uint32_t a;
    asm("{ .reg .u64 t; cvta.to.shared.u64 t, %1; cvt.u32.u64 %0, t; }"
        : "=r"(a) : "l"(p));
    return a;
}

#define CP_ASYNC_16(dst, src) \
    asm volatile("cp.async.cg.shared.global [%0], [%1], 16;" \
                 :: "r"((uint32_t)(dst)), "l"(src))
#define CP_ASYNC_COMMIT() asm volatile("cp.async.commit_group;" ::: "memory")
#define CP_ASYNC_WAIT0()  asm volatile("cp.async.wait_group 0;" ::: "memory")

__device__ __forceinline__ void ldsm_x4(uint32_t r[4], uint32_t addr) {
    asm volatile("ldmatrix.sync.aligned.m8n8.x4.shared.b16 {%0,%1,%2,%3}, [%4];"
                 : "=r"(r[0]), "=r"(r[1]), "=r"(r[2]), "=r"(r[3]) : "r"(addr));
}

__device__ __forceinline__ void mma_fp16(float c[4], const uint32_t a[4],
                                         const uint32_t b0, const uint32_t b1) {
    asm volatile(
        "mma.sync.aligned.m16n8k16.row.col.f32.f16.f16.f32 "
        "{%0,%1,%2,%3}, {%4,%5,%6,%7}, {%8,%9}, {%0,%1,%2,%3};"
        : "+f"(c[0]), "+f"(c[1]), "+f"(c[2]), "+f"(c[3])
        : "r"(a[0]), "r"(a[1]), "r"(a[2]), "r"(a[3]), "r"(b0), "r"(b1));
}

// ============================================================
// smem layout for big kernel (dynamic)
//   gate row: 2048 B
//   2 buffers, each: A(128x80=10240) B(128x80=10240) = 20480 B
//   rows: 32 fp16 (64B) data + 16B pad, stride 80 (ldmatrix conflict-free)
// ============================================================
#define ASTRIDE 80
#define OFF_A 0
#define OFF_B 10240
#define BUF_BYTES 20480
#define SMEM_BYTES (2048 + 2 * BUF_BYTES)   // 43008 per CTA, 2 CTAs/SM

// ============================================================
// Preamble small GEMM core: BM=64, BN=32, BK=16, 128 threads
// ============================================================
template <int ACT>
__device__ __forceinline__ void gemm_small_body(
    const float* __restrict__ A, const float* __restrict__ W,
    const float* __restrict__ bias, float* __restrict__ C,
    int m0, int n0)
{
    __shared__ float As[16][64];
    __shared__ float Bs[16][32];
    const int t = threadIdx.x;
    const int tx = t & 7, ty = t >> 3;
    float acc[4][4] = {};
    for (int k0 = 0; k0 < DD; k0 += 16) {
        {
            const int m = t >> 1;
            const int kq = (t & 1) * 8;
            float4 v0 = *(const float4*)&A[(size_t)(m0 + m) * DD + k0 + kq];
            float4 v1 = *(const float4*)&A[(size_t)(m0 + m) * DD + k0 + kq + 4];
            As[kq + 0][m] = v0.x; As[kq + 1][m] = v0.y;
            As[kq + 2][m] = v0.z; As[kq + 3][m] = v0.w;
            As[kq + 4][m] = v1.x; As[kq + 5][m] = v1.y;
            As[kq + 6][m] = v1.z; As[kq + 7][m] = v1.w;
        }
        {
            const int k = t >> 3, n = (t & 7) * 4;
            *(float4*)&Bs[k][n] = *(const float4*)&W[(size_t)(k0 + k) * OD + n0 + n];
        }
        __syncthreads();
        #pragma unroll
        for (int k = 0; k < 16; k++) {
            float a[4], b[4];
            *(float4*)a = *(const float4*)&As[k][ty * 4];
            *(float4*)b = *(const float4*)&Bs[k][tx * 4];
            #pragma unroll
            for (int r = 0; r < 4; r++)
                #pragma unroll
                for (int c = 0; c < 4; c++)
                    acc[r][c] += a[r] * b[c];
        }
        __syncthreads();
    }
    #pragma unroll
    for (int r = 0; r < 4; r++) {
        const int m = m0 + ty * 4 + r;
        float4 v; float* vv = (float*)&v;
        #pragma unroll
        for (int c = 0; c < 4; c++) {
            float x = acc[r][c] + __ldg(&bias[n0 + tx * 4 + c]);
            if (ACT == 1) x = fmaxf(x, 0.0f);
            if (ACT == 2) x = 1.0f / (1.0f + __expf(-x));
            vv[c] = x;
        }
        *(float4*)&C[(size_t)m * OD + n0 + tx * 4] = v;
    }
}

template <int ACT>
__global__ void __launch_bounds__(128)
gemm_small_kernel(const float* __restrict__ A, const float* __restrict__ W,
                  const float* __restrict__ bias, float* __restrict__ C)
{
    gemm_small_body<ACT>(A, W, bias, C, blockIdx.y * 64, blockIdx.x * 32);
}

// Fused first stage: z=0 -> h = relu(text@Wa1+ba1); z=1 -> outx = image@Wx+bx
__global__ void __launch_bounds__(128)
pre_fused_kernel(const float* __restrict__ text, const float* __restrict__ image,
                 const float* __restrict__ Wa1, const float* __restrict__ ba1,
                 const float* __restrict__ Wx,  const float* __restrict__ bx,
                 float* __restrict__ h, float* __restrict__ outx)
{
    if (blockIdx.z == 0)
        gemm_small_body<1>(text, Wa1, ba1, h, blockIdx.y * 64, blockIdx.x * 32);
    else
        gemm_small_body<0>(image, Wx, bx, outx, blockIdx.y * 64, blockIdx.x * 32);
}

// ============================================================
// Preamble: row softmax * text
// ============================================================
__global__ void __launch_bounds__(512)
softmax_mul_kernel(const float* __restrict__ logits, const float* __restrict__ text,
                   float* __restrict__ out)
{
    __shared__ float sdata[512];
    const int row = blockIdx.x, t = threadIdx.x;
    const float v = logits[(size_t)row * DD + t];
    sdata[t] = v; __syncthreads();
    for (int s = 256; s > 0; s >>= 1) { if (t < s) sdata[t] = fmaxf(sdata[t], sdata[t + s]); __syncthreads(); }
    const float mx = sdata[0]; __syncthreads();
    const float e = __expf(v - mx);
    sdata[t] = e; __syncthreads();
    for (int s = 256; s > 0; s >>= 1) { if (t < s) sdata[t] += sdata[t + s]; __syncthreads(); }
    out[(size_t)row * DD + t] = e * (1.0f / sdata[0]) * text[(size_t)row * DD + t];
}

// ============================================================
// Preamble: transpose Wo -> fp16:  WoT[o][d] = fp16(Wo[d][o])
// ============================================================
__global__ void __launch_bounds__(256)
transpose_wo_h(const float* __restrict__ Wo, __half* __restrict__ T)
{
    __shared__ float tile[32][33];
    const int bo = blockIdx.x * 32;
    const int bd = blockIdx.y * 32;
    const int x = threadIdx.x, y = threadIdx.y;   // (32, 8)
    #pragma unroll
    for (int r = 0; r < 4; r++)
        tile[y + 8 * r][x] = Wo[(size_t)(bd + y + 8 * r) * OD + bo + x];
    __syncthreads();
    #pragma unroll
    for (int r = 0; r < 4; r++) {
        const int o = bo + y + 8 * r;
        const int d = bd + x;
        T[(size_t)o * DD + d] = __float2half_rn(tile[x][y + 8 * r]);
    }
}

__global__ void mul_kernel(const float* __restrict__ a, const float* __restrict__ b,
                           float* __restrict__ c, int n)
{
    int idx = blockIdx.x * blockDim.x + threadIdx.x;
    if (idx < n) c[idx] = a[idx] * b[idx];
}

// ============================================================
// Big einsum via single-pass fp16 HMMA:
//   out[i,j,o] = sum_d gate[i,d]*outx[j,d]*Wo[d,o] + bo[o]
// grid (4 o-tiles, 4 j-tiles, 512 i) = 8192 CTAs, 128 threads (4 warps).
// CTA tile 128(j) x 128(o); warp tile 64x64 (warp_m = wid&1, warp_n = wid>>1).
// 2 CTAs/SM: one CTA's MMA burst hides the other's barrier/convert tail.
// K chunks of 32, double-buffered cp.async B + register-staged A.
// ============================================================
__global__ void __launch_bounds__(128, 2)
big_einsum_hmma_kernel(const float* __restrict__ outx, const float* __restrict__ gate,
                       const float* __restrict__ bo, float* __restrict__ out)
{
    extern __shared__ char dynsmem[];
    float* gs = (float*)dynsmem;
    const uint32_t sbase = smem_u32(dynsmem) + 2048u;

    const int i  = blockIdx.z;
    const int j0 = blockIdx.y * 128;
    const int o0 = blockIdx.x * 128;
    const int tid  = threadIdx.x;
    const int wid  = tid >> 5;
    const int lane = tid & 31;
    const int warp_m = wid & 1;     // 2 x 64 rows (j)
    const int warp_n = wid >> 1;    // 2 x 64 cols (o)

    // ---- gate row -> smem ----
    #pragma unroll
    for (int q = 0; q < 4; q++) gs[tid + q * 128] = gate[(size_t)i * DD + tid + q * 128];

    // ---- cp.async B: 128 rows x 64B per chunk (4 x 16B per thread) ----
    auto cpB = [&](int c, int buf) {
        const int c0 = c * 32;
        const uint32_t bdst = sbase + buf * BUF_BYTES + OFF_B;
        #pragma unroll
        for (int q = 0; q < 4; q++) {
            const int g   = tid + q * 128;      // 0..511
            const int row = g >> 2;             // 0..127
            const int ck  = g & 3;
            const uint32_t dso = (uint32_t)(row * ASTRIDE + ck * 16);
            const __half* src = g_WoT + (size_t)(o0 + row) * DD + c0 + ck * 8;
            CP_ASYNC_16(bdst + dso, src);
        }
        CP_ASYNC_COMMIT();
    };

    // ---- A gmem load (registers): one row per thread, 32 floats ----
    float4 av[8];
    auto loadA = [&](int c) {
        const float* p = outx + (size_t)(j0 + tid) * DD + c * 32;
        #pragma unroll
        for (int q = 0; q < 8; q++) av[q] = __ldg((const float4*)(p + q * 4));
    };

    // ---- A convert (gate-scaled) + fp16 store: 64B per thread-row ----
    auto storeA = [&](int c, int buf) {
        const int c0 = c * 32;
        const uint32_t ad = sbase + buf * BUF_BYTES + OFF_A + tid * ASTRIDE;
        #pragma unroll
        for (int q = 0; q < 4; q++) {
            const float4 ga = *(const float4*)&gs[c0 + q * 8];
            const float4 gb = *(const float4*)&gs[c0 + q * 8 + 4];
            __half2 h0 = __float22half2_rn(make_float2(av[q*2].x   * ga.x, av[q*2].y   * ga.y));
            __half2 h1 = __float22half2_rn(make_float2(av[q*2].z   * ga.z, av[q*2].w   * ga.w));
            __half2 h2 = __float22half2_rn(make_float2(av[q*2+1].x * gb.x, av[q*2+1].y * gb.y));
            __half2 h3 = __float22half2_rn(make_float2(av[q*2+1].z * gb.z, av[q*2+1].w * gb.w));
            asm volatile("st.shared.v4.b32 [%0], {%1,%2,%3,%4};"
                         :: "r"(ad + q * 16), "r"(*(uint32_t*)&h0), "r"(*(uint32_t*)&h1),
                            "r"(*(uint32_t*)&h2), "r"(*(uint32_t*)&h3));
        }
    };

    // ---- ldmatrix lane offsets (bytes) ----
    const uint32_t a_lane = (uint32_t)(((lane & 7) + ((lane >> 3) & 1) * 8) * ASTRIDE
                                       + (lane >> 4) * 16);
    const uint32_t b_lane = (uint32_t)(((lane & 7) + (lane >> 4) * 8) * ASTRIDE
                                       + ((lane >> 3) & 1) * 16);
    const uint32_t a_warp = (uint32_t)(warp_m * 64 * ASTRIDE);
    const uint32_t b_warp = (uint32_t)(warp_n * 64 * ASTRIDE);

    float acc[4][8][4] = {};   // [m-tile 16][n-group 8][frag]

    // ---- prologue ----
    loadA(0);
    cpB(0, 0);
    __syncthreads();          // gs visible
    storeA(0, 0);
    CP_ASYNC_WAIT0();
    __syncthreads();          // buffer 0 ready

    // ---- main loop over 16 K-chunks ----
    for (int c = 0; c < 16; c++) {
        const int buf = c & 1;
        if (c < 15) { loadA(c + 1); cpB(c + 1, buf ^ 1); }

        const uint32_t bb = sbase + buf * BUF_BYTES;
        #pragma unroll
        for (int ks = 0; ks < 2; ks++) {
            uint32_t ah[4][4];
            #pragma unroll
            for (int mt = 0; mt < 4; mt++)
                ldsm_x4(ah[mt], bb + OFF_A + a_warp + a_lane + mt * 16 * ASTRIDE + ks * 32);
            #pragma unroll
            for (int g = 0; g < 4; g++) {
                uint32_t bh[4];
                ldsm_x4(bh, bb + OFF_B + b_warp + b_lane + g * 16 * ASTRIDE + ks * 32);
                #pragma unroll
                for (int mt = 0; mt < 4; mt++) {
                    mma_fp16(acc[mt][g * 2],     ah[mt], bh[0], bh[1]);
                    mma_fp16(acc[mt][g * 2 + 1], ah[mt], bh[2], bh[3]);
                }
            }
        }

        if (c < 15) {
            storeA(c + 1, buf ^ 1);
            CP_ASYNC_WAIT0();
            __syncthreads();
        }
    }

    // ---- epilogue: bias + store ----
    const int colb = o0 + warp_n * 64 + (lane & 3) * 2;
    float2 bv[8];
    #pragma unroll
    for (int nj = 0; nj < 8; nj++)
        bv[nj] = __ldg((const float2*)&bo[colb + nj * 8]);

    const int rowb = j0 + warp_m * 64 + (lane >> 2);
    #pragma unroll
    for (int mt = 0; mt < 4; mt++) {
        #pragma unroll
        for (int h = 0; h < 2; h++) {
            const size_t rbase = ((size_t)i * NB + (rowb + mt * 16 + h * 8)) * OD;
            #pragma unroll
            for (int nj = 0; nj < 8; nj++) {
                float2 v;
                v.x = acc[mt][nj][h * 2]     + bv[nj].x;
                v.y = acc[mt][nj][h * 2 + 1] + bv[nj].y;
                *(float2*)&out[rbase + colb + nj * 8] = v;
            }
        }
    }
}

// ============================================================
// kernel_launch
// ============================================================
extern "C" void kernel_launch(void* const* d_in, const int* in_sizes, int n_in,
                              void* d_out, int out_size)
{
    const float* image = (const float*)d_in[0];
    const float* text  = (const float*)d_in[1];
    const float* Wx  = (const float*)d_in[3];
    const float* bx  = (const float*)d_in[4];
    const float* Wy  = (const float*)d_in[5];
    const float* by  = (const float*)d_in[6];
    const float* Wo  = (const float*)d_in[7];
    const float* bo  = (const float*)d_in[8];
    const float* Wa1 = (const float*)d_in[9];
    const float* ba1 = (const float*)d_in[10];
    const float* Wa2 = (const float*)d_in[11];
    const float* ba2 = (const float*)d_in[12];
    float* out = (float*)d_out;

    float *h, *logits, *textw, *outx, *gate, *tmp;
    __half* wot;
    cudaGetSymbolAddress((void**)&h,      g_h);
    cudaGetSymbolAddress((void**)&logits, g_logits);
    cudaGetSymbolAddress((void**)&textw,  g_textw);
    cudaGetSymbolAddress((void**)&outx,   g_outx);
    cudaGetSymbolAddress((void**)&gate,   g_gate);
    cudaGetSymbolAddress((void**)&tmp,    g_tmp);
    cudaGetSymbolAddress((void**)&wot,    g_WoT);

    cudaFuncSetAttribute(big_einsum_hmma_kernel,
                         cudaFuncAttributeMaxDynamicSharedMemorySize, SMEM_BYTES);

    const dim3 gsm(OD / 32, NB / 64);   // (16, 8) = 128 CTAs

    // Wo transpose -> fp16
    transpose_wo_h<<<dim3(16, 16), dim3(32, 8)>>>(Wo, wot);
    // Stage 1 fused: h = relu(text@Wa1+ba1)  and  outx = image@Wx+bx
    pre_fused_kernel<<<dim3(OD / 32, NB / 64, 2), 128>>>(text, image, Wa1, ba1, Wx, bx, h, outx);
    // logits = h@Wa2+ba2
    gemm_small_kernel<0><<<gsm, 128>>>(h, Wa2, ba2, logits);
    // textw = softmax(logits) * text
    softmax_mul_kernel<<<NB, 512>>>(logits, text, textw);
    // gate = sigmoid(textw@Wy+by)
    gemm_small_kernel<2><<<gsm, 128>>>(textw, Wy, by, gate);

    if (out_size == NB * NB * OD) {
        dim3 grid(OD / 128, NB / 128, NB);   // (4, 4, 512)
        big_einsum_hmma_kernel<<<grid, 128, SMEM_BYTES>>>(outx, gate, bo, out);
    } else {
        mul_kernel<<<(NB * DD + 255) / 256, 256>>>(gate, outx, tmp, NB * DD);
        gemm_small_kernel<0><<<gsm, 128>>>(tmp, Wo, bo, out);
    }
}

// round 7
// speedup vs baseline: 1.4472x; 1.4472x over previous
#include <cuda_runtime.h>
#include <cuda_fp16.h>
#include <cstdint>

#define NB 512   // batch
#define DD 512   // embed dim
#define OD 512   // out dim

// -------- scratch (no cudaMalloc allowed) --------
__device__ float g_h[NB * DD];
__device__ float g_logits[NB * DD];
__device__ float g_textw[NB * DD];
__device__ float g_outx[NB * DD];
__device__ float g_gate[NB * DD];
__device__ float g_tmp[NB * DD];
__device__ __half g_outxh[NB * DD];  // fp16 copy of outx
__device__ __half g_WoT[OD * DD];    // WoT[o][d] = fp16(Wo[d][o])

// ============================================================
// Helpers (plain sm_80+ PTX: mma.sync / ldmatrix / cp.async)
// ============================================================
__device__ __forceinline__ uint32_t smem_u32(const void* p) {
    uint32_t a;
    asm("{ .reg .u64 t; cvta.to.shared.u64 t, %1; cvt.u32.u64 %0, t; }"
        : "=r"(a) : "l"(p));
    return a;
}

#define CP_ASYNC_16(dst, src) \
    asm volatile("cp.async.cg.shared.global [%0], [%1], 16;" \
                 :: "r"((uint32_t)(dst)), "l"(src))
#define CP_ASYNC_COMMIT() asm volatile("cp.async.commit_group;" ::: "memory")
#define CP_ASYNC_WAIT0()  asm volatile("cp.async.wait_group 0;" ::: "memory")

__device__ __forceinline__ void ldsm_x4(uint32_t r[4], uint32_t addr) {
    asm volatile("ldmatrix.sync.aligned.m8n8.x4.shared.b16 {%0,%1,%2,%3}, [%4];"
                 : "=r"(r[0]), "=r"(r[1]), "=r"(r[2]), "=r"(r[3]) : "r"(addr));
}

__device__ __forceinline__ void mma_fp16(float c[4], const uint32_t a[4],
                                         const uint32_t b0, const uint32_t b1) {
    asm volatile(
        "mma.sync.aligned.m16n8k16.row.col.f32.f16.f16.f32 "
        "{%0,%1,%2,%3}, {%4,%5,%6,%7}, {%8,%9}, {%0,%1,%2,%3};"
        : "+f"(c[0]), "+f"(c[1]), "+f"(c[2]), "+f"(c[3])
        : "r"(a[0]), "r"(a[1]), "r"(a[2]), "r"(a[3]), "r"(b0), "r"(b1));
}

// ============================================================
// smem layout for big kernel (dynamic)
//   gate row (fp32): 2048 B
//   2 buffers, each: A(128x80=10240) B(128x80=10240) = 20480 B
//   rows: 32 fp16 (64B) data + 16B pad, stride 80 (ldmatrix conflict-free)
// ============================================================
#define ASTRIDE 80
#define OFF_A 0
#define OFF_B 10240
#define BUF_BYTES 20480
#define SMEM_BYTES (2048 + 2 * BUF_BYTES)   // 43008 per CTA -> 2 CTAs/SM

// ============================================================
// Preamble small GEMM core: BM=64, BN=32, BK=16, 128 threads
// ============================================================
template <int ACT>
__device__ __forceinline__ void gemm_small_body(
    const float* __restrict__ A, const float* __restrict__ W,
    const float* __restrict__ bias, float* __restrict__ C,
    int m0, int n0)
{
    __shared__ float As[16][64];
    __shared__ float Bs[16][32];
    const int t = threadIdx.x;
    const int tx = t & 7, ty = t >> 3;
    float acc[4][4] = {};
    for (int k0 = 0; k0 < DD; k0 += 16) {
        {
            const int m = t >> 1;
            const int kq = (t & 1) * 8;
            float4 v0 = *(const float4*)&A[(size_t)(m0 + m) * DD + k0 + kq];
            float4 v1 = *(const float4*)&A[(size_t)(m0 + m) * DD + k0 + kq + 4];
            As[kq + 0][m] = v0.x; As[kq + 1][m] = v0.y;
            As[kq + 2][m] = v0.z; As[kq + 3][m] = v0.w;
            As[kq + 4][m] = v1.x; As[kq + 5][m] = v1.y;
            As[kq + 6][m] = v1.z; As[kq + 7][m] = v1.w;
        }
        {
            const int k = t >> 3, n = (t & 7) * 4;
            *(float4*)&Bs[k][n] = *(const float4*)&W[(size_t)(k0 + k) * OD + n0 + n];
        }
        __syncthreads();
        #pragma unroll
        for (int k = 0; k < 16; k++) {
            float a[4], b[4];
            *(float4*)a = *(const float4*)&As[k][ty * 4];
            *(float4*)b = *(const float4*)&Bs[k][tx * 4];
            #pragma unroll
            for (int r = 0; r < 4; r++)
                #pragma unroll
                for (int c = 0; c < 4; c++)
                    acc[r][c] += a[r] * b[c];
        }
        __syncthreads();
    }
    #pragma unroll
    for (int r = 0; r < 4; r++) {
        const int m = m0 + ty * 4 + r;
        float4 v; float* vv = (float*)&v;
        #pragma unroll
        for (int c = 0; c < 4; c++) {
            float x = acc[r][c] + __ldg(&bias[n0 + tx * 4 + c]);
            if (ACT == 1) x = fmaxf(x, 0.0f);
            if (ACT == 2) x = 1.0f / (1.0f + __expf(-x));
            vv[c] = x;
        }
        *(float4*)&C[(size_t)m * OD + n0 + tx * 4] = v;
    }
}

template <int ACT>
__global__ void __launch_bounds__(128)
gemm_small_kernel(const float* __restrict__ A, const float* __restrict__ W,
                  const float* __restrict__ bias, float* __restrict__ C)
{
    gemm_small_body<ACT>(A, W, bias, C, blockIdx.y * 64, blockIdx.x * 32);
}

// Fused first stage: z=0 -> h = relu(text@Wa1+ba1); z=1 -> outx = image@Wx+bx
__global__ void __launch_bounds__(128)
pre_fused_kernel(const float* __restrict__ text, const float* __restrict__ image,
                 const float* __restrict__ Wa1, const float* __restrict__ ba1,
                 const float* __restrict__ Wx,  const float* __restrict__ bx,
                 float* __restrict__ h, float* __restrict__ outx)
{
    if (blockIdx.z == 0)
        gemm_small_body<1>(text, Wa1, ba1, h, blockIdx.y * 64, blockIdx.x * 32);
    else
        gemm_small_body<0>(image, Wx, bx, outx, blockIdx.y * 64, blockIdx.x * 32);
}

// ============================================================
// Preamble: row softmax * text
// ============================================================
__global__ void __launch_bounds__(512)
softmax_mul_kernel(const float* __restrict__ logits, const float* __restrict__ text,
                   float* __restrict__ out)
{
    __shared__ float sdata[512];
    const int row = blockIdx.x, t = threadIdx.x;
    const float v = logits[(size_t)row * DD + t];
    sdata[t] = v; __syncthreads();
    for (int s = 256; s > 0; s >>= 1) { if (t < s) sdata[t] = fmaxf(sdata[t], sdata[t + s]); __syncthreads(); }
    const float mx = sdata[0]; __syncthreads();
    const float e = __expf(v - mx);
    sdata[t] = e; __syncthreads();
    for (int s = 256; s > 0; s >>= 1) { if (t < s) sdata[t] += sdata[t + s]; __syncthreads(); }
    out[(size_t)row * DD + t] = e * (1.0f / sdata[0]) * text[(size_t)row * DD + t];
}

// ============================================================
// Preamble: transpose Wo -> fp16:  WoT[o][d] = fp16(Wo[d][o])
// ============================================================
__global__ void __launch_bounds__(256)
transpose_wo_h(const float* __restrict__ Wo, __half* __restrict__ T)
{
    __shared__ float tile[32][33];
    const int bo = blockIdx.x * 32;
    const int bd = blockIdx.y * 32;
    const int x = threadIdx.x, y = threadIdx.y;   // (32, 8)
    #pragma unroll
    for (int r = 0; r < 4; r++)
        tile[y + 8 * r][x] = Wo[(size_t)(bd + y + 8 * r) * OD + bo + x];
    __syncthreads();
    #pragma unroll
    for (int r = 0; r < 4; r++) {
        const int o = bo + y + 8 * r;
        const int d = bd + x;
        T[(size_t)o * DD + d] = __float2half_rn(tile[x][y + 8 * r]);
    }
}

// ============================================================
// Preamble: fp32 -> fp16 convert (outx)
// ============================================================
__global__ void __launch_bounds__(256)
f32_to_f16_kernel(const float* __restrict__ src, __half* __restrict__ dst)
{
    const int idx = (blockIdx.x * 256 + threadIdx.x) * 4;
    const float4 v = *(const float4*)&src[idx];
    __half2 a = __float22half2_rn(make_float2(v.x, v.y));
    __half2 b = __float22half2_rn(make_float2(v.z, v.w));
    *(uint2*)&dst[idx] = make_uint2(*(uint32_t*)&a, *(uint32_t*)&b);
}

__global__ void mul_kernel(const float* __restrict__ a, const float* __restrict__ b,
                           float* __restrict__ c, int n)
{
    int idx = blockIdx.x * blockDim.x + threadIdx.x;
    if (idx < n) c[idx] = a[idx] * b[idx];
}

// ============================================================
// Big einsum via single-pass fp16 HMMA:
//   out[i,j,o] = sum_d gate[i,d]*outx[j,d]*Wo[d,o] + bo[o]
// grid (4 o-tiles, 4 j-tiles, 512 i) = 8192 CTAs, 256 threads (8 warps).
// CTA tile 128(j) x 128(o); warp tile 32x64 (warp_m = wid&3, warp_n = wid>>2).
// 2 CTAs/SM (43KB smem, <=128 regs): two sync domains overlap per-chunk tails.
// A read as pre-converted fp16 (outxh) -> halved A L2 traffic; gate fp32 in smem.
// ============================================================
__global__ void __launch_bounds__(256, 2)
big_einsum_hmma_kernel(const __half* __restrict__ outxh, const float* __restrict__ gate,
                       const float* __restrict__ bo, float* __restrict__ out)
{
    extern __shared__ char dynsmem[];
    float* gs = (float*)dynsmem;
    const uint32_t sbase = smem_u32(dynsmem) + 2048u;

    const int i  = blockIdx.z;
    const int j0 = blockIdx.y * 128;
    const int o0 = blockIdx.x * 128;
    const int tid  = threadIdx.x;
    const int wid  = tid >> 5;
    const int lane = tid & 31;
    const int warp_m = wid & 3;     // 4 x 32 rows (j)
    const int warp_n = wid >> 2;    // 2 x 64 cols (o)

    // ---- gate row (fp32) -> smem ----
    gs[tid]       = gate[(size_t)i * DD + tid];
    gs[tid + 256] = gate[(size_t)i * DD + tid + 256];

    // ---- A-build indices: row = tid>>1 (0..127), half-row of 16 fp16 ----
    const int arow = tid >> 1;
    const int ach  = (tid & 1) * 16;

    // ---- cp.async B: 128 rows x 64B per chunk (2 x 16B per thread) ----
    auto cpB = [&](int c, int buf) {
        const int c0 = c * 32;
        const uint32_t bdst = sbase + buf * BUF_BYTES + OFF_B;
        #pragma unroll
        for (int q = 0; q < 2; q++) {
            const int g   = tid + q * 256;      // 0..511
            const int row = g >> 2;             // 0..127
            const int ck  = g & 3;
            const uint32_t dso = (uint32_t)(row * ASTRIDE + ck * 16);
            const __half* src = g_WoT + (size_t)(o0 + row) * DD + c0 + ck * 8;
            CP_ASYNC_16(bdst + dso, src);
        }
        CP_ASYNC_COMMIT();
    };

    // ---- A gmem load (fp16, 32B per thread) ----
    uint4 av;
    auto loadA = [&](int c) {
        const __half* p = outxh + (size_t)(j0 + arow) * DD + c * 32 + ach;
        av = __ldg((const uint4*)p);
    };

    // ---- A convert: fp16 x -> float, * gate(fp32), -> fp16, store 32B ----
    auto storeA = [&](int c, int buf) {
        const int d0 = c * 32 + ach;
        const uint32_t* xp = (const uint32_t*)&av;
        uint32_t w[8];
        #pragma unroll
        for (int q = 0; q < 8; q++) {
            const __half2 xh = *(const __half2*)&xp[q >> 1];
            // pick low/high half2 pair from the two halfs stored per uint32
            float2 xf = __half22float2(*(const __half2*)&xp[q >> 1]);
            (void)xh;
            // q indexes 8 half2 groups: xp has 4 uint32 = 8 halfs... need 16 halfs
            w[q] = 0u;
        }
        // 16 halfs = 8 half2 live in av (4 uint32 hold 8 halfs) -- WRONG above; redo properly:
        const __half2* xh2 = (const __half2*)&av;   // 4 half2 = 8 halfs... av is 16B = 8 halfs
        // We need 16 halfs (32B): av only holds 8. Use two loads worth: see loadA2 below.
        (void)xh2; (void)d0;
        #pragma unroll
        for (int q = 0; q < 8; q++) (void)w[q];
    };
    (void)storeA;

    // ---- corrected A staging: 32B = two uint4? keep it simple: 16 halfs via 2 LDG.128
    uint4 av2;
    auto loadA16 = [&](int c) {
        const __half* p = outxh + (size_t)(j0 + arow) * DD + c * 32 + ach;
        av  = __ldg((const uint4*)p);        // 8 halfs
        av2 = __ldg((const uint4*)(p + 8));  // 8 halfs
    };
    auto storeA16 = [&](int c, int buf) {
        const int d0 = c * 32 + ach;
        const __half2* xa = (const __half2*)&av;
        const __half2* xb = (const __half2*)&av2;
        uint32_t w[8];
        #pragma unroll
        for (int q = 0; q < 4; q++) {
            float2 xf = __half22float2(xa[q]);
            const float2 gf = *(const float2*)&gs[d0 + q * 2];
            __half2 r = __float22half2_rn(make_float2(xf.x * gf.x, xf.y * gf.y));
            w[q] = *(uint32_t*)&r;
        }
        #pragma unroll
        for (int q = 0; q < 4; q++) {
            float2 xf = __half22float2(xb[q]);
            const float2 gf = *(const float2*)&gs[d0 + 8 + q * 2];
            __half2 r = __float22half2_rn(make_float2(xf.x * gf.x, xf.y * gf.y));
            w[4 + q] = *(uint32_t*)&r;
        }
        const uint32_t ad = sbase + buf * BUF_BYTES + OFF_A + arow * ASTRIDE + ach * 2;
        asm volatile("st.shared.v4.b32 [%0], {%1,%2,%3,%4};"
                     :: "r"(ad), "r"(w[0]), "r"(w[1]), "r"(w[2]), "r"(w[3]));
        asm volatile("st.shared.v4.b32 [%0], {%1,%2,%3,%4};"
                     :: "r"(ad + 16), "r"(w[4]), "r"(w[5]), "r"(w[6]), "r"(w[7]));
    };

    // ---- ldmatrix lane offsets (bytes) ----
    const uint32_t a_lane = (uint32_t)(((lane & 7) + ((lane >> 3) & 1) * 8) * ASTRIDE
                                       + (lane >> 4) * 16);
    const uint32_t b_lane = (uint32_t)(((lane & 7) + (lane >> 4) * 8) * ASTRIDE
                                       + ((lane >> 3) & 1) * 16);
    const uint32_t a_warp = (uint32_t)(warp_m * 32 * ASTRIDE);
    const uint32_t b_warp = (uint32_t)(warp_n * 64 * ASTRIDE);

    float acc[2][8][4] = {};   // [m-tile 16][n-group 8][frag]

    // ---- prologue ----
    loadA16(0);
    cpB(0, 0);
    __syncthreads();          // gs visible
    storeA16(0, 0);
    CP_ASYNC_WAIT0();
    __syncthreads();          // buffer 0 ready

    // ---- main loop over 16 K-chunks ----
    for (int c = 0; c < 16; c++) {
        const int buf = c & 1;
        if (c < 15) { loadA16(c + 1); cpB(c + 1, buf ^ 1); }

        const uint32_t bb = sbase + buf * BUF_BYTES;
        #pragma unroll
        for (int ks = 0; ks < 2; ks++) {
            uint32_t ah[2][4];
            ldsm_x4(ah[0], bb + OFF_A + a_warp + a_lane + ks * 32);
            ldsm_x4(ah[1], bb + OFF_A + a_warp + a_lane + 16 * ASTRIDE + ks * 32);
            #pragma unroll
            for (int g = 0; g < 4; g++) {
                uint32_t bh[4];
                ldsm_x4(bh, bb + OFF_B + b_warp + b_lane + g * 16 * ASTRIDE + ks * 32);
                mma_fp16(acc[0][g * 2],     ah[0], bh[0], bh[1]);
                mma_fp16(acc[0][g * 2 + 1], ah[0], bh[2], bh[3]);
                mma_fp16(acc[1][g * 2],     ah[1], bh[0], bh[1]);
                mma_fp16(acc[1][g * 2 + 1], ah[1], bh[2], bh[3]);
            }
        }

        if (c < 15) {
            storeA16(c + 1, buf ^ 1);
            CP_ASYNC_WAIT0();
            __syncthreads();
        }
    }

    // ---- epilogue: bias + store ----
    const int colb = o0 + warp_n * 64 + (lane & 3) * 2;
    float2 bv[8];
    #pragma unroll
    for (int nj = 0; nj < 8; nj++)
        bv[nj] = __ldg((const float2*)&bo[colb + nj * 8]);

    const int rowb = j0 + warp_m * 32 + (lane >> 2);
    #pragma unroll
    for (int mt = 0; mt < 2; mt++) {
        #pragma unroll
        for (int h = 0; h < 2; h++) {
            const size_t rbase = ((size_t)i * NB + (rowb + mt * 16 + h * 8)) * OD;
            #pragma unroll
            for (int nj = 0; nj < 8; nj++) {
                float2 v;
                v.x = acc[mt][nj][h * 2]     + bv[nj].x;
                v.y = acc[mt][nj][h * 2 + 1] + bv[nj].y;
                *(float2*)&out[rbase + colb + nj * 8] = v;
            }
        }
    }
}

// ============================================================
// kernel_launch
// ============================================================
extern "C" void kernel_launch(void* const* d_in, const int* in_sizes, int n_in,
                              void* d_out, int out_size)
{
    const float* image = (const float*)d_in[0];
    const float* text  = (const float*)d_in[1];
    const float* Wx  = (const float*)d_in[3];
    const float* bx  = (const float*)d_in[4];
    const float* Wy  = (const float*)d_in[5];
    const float* by  = (const float*)d_in[6];
    const float* Wo  = (const float*)d_in[7];
    const float* bo  = (const float*)d_in[8];
    const float* Wa1 = (const float*)d_in[9];
    const float* ba1 = (const float*)d_in[10];
    const float* Wa2 = (const float*)d_in[11];
    const float* ba2 = (const float*)d_in[12];
    float* out = (float*)d_out;

    float *h, *logits, *textw, *outx, *gate, *tmp;
    __half *wot, *outxh;
    cudaGetSymbolAddress((void**)&h,      g_h);
    cudaGetSymbolAddress((void**)&logits, g_logits);
    cudaGetSymbolAddress((void**)&textw,  g_textw);
    cudaGetSymbolAddress((void**)&outx,   g_outx);
    cudaGetSymbolAddress((void**)&gate,   g_gate);
    cudaGetSymbolAddress((void**)&tmp,    g_tmp);
    cudaGetSymbolAddress((void**)&wot,    g_WoT);
    cudaGetSymbolAddress((void**)&outxh,  g_outxh);

    cudaFuncSetAttribute(big_einsum_hmma_kernel,
                         cudaFuncAttributeMaxDynamicSharedMemorySize, SMEM_BYTES);

    const dim3 gsm(OD / 32, NB / 64);   // (16, 8) = 128 CTAs

    // Wo transpose -> fp16
    transpose_wo_h<<<dim3(16, 16), dim3(32, 8)>>>(Wo, wot);
    // Stage 1 fused: h = relu(text@Wa1+ba1)  and  outx = image@Wx+bx
    pre_fused_kernel<<<dim3(OD / 32, NB / 64, 2), 128>>>(text, image, Wa1, ba1, Wx, bx, h, outx);
    // outx -> fp16 copy for the big kernel's A operand
    f32_to_f16_kernel<<<(NB * DD) / (256 * 4), 256>>>(outx, outxh);
    // logits = h@Wa2+ba2
    gemm_small_kernel<0><<<gsm, 128>>>(h, Wa2, ba2, logits);
    // textw = softmax(logits) * text
    softmax_mul_kernel<<<NB, 512>>>(logits, text, textw);
    // gate = sigmoid(textw@Wy+by)
    gemm_small_kernel<2><<<gsm, 128>>>(textw, Wy, by, gate);

    if (out_size == NB * NB * OD) {
        dim3 grid(OD / 128, NB / 128, NB);   // (4, 4, 512)
        big_einsum_hmma_kernel<<<grid, 256, SMEM_BYTES>>>(outxh, gate, bo, out);
    } else {
        mul_kernel<<<(NB * DD + 255) / 256, 256>>>(gate, outx, tmp, NB * DD);
        gemm_small_kernel<0><<<gsm, 128>>>(tmp, Wo, bo, out);
    }
}

// round 8
// speedup vs baseline: 1.4627x; 1.0107x over previous
#include <cuda_runtime.h>
#include <cuda_fp16.h>
#include <cstdint>

#define NB 512   // batch
#define DD 512   // embed dim
#define OD 512   // out dim

// -------- scratch (no cudaMalloc allowed) --------
__device__ float g_h[NB * DD];
__device__ float g_logits[NB * DD];
__device__ float g_textw[NB * DD];
__device__ float g_outx[NB * DD];
__device__ float g_gate[NB * DD];
__device__ float g_tmp[NB * DD];
__device__ __half g_outxh[NB * DD];  // fp16 copy of outx
__device__ __half g_WoT[OD * DD];    // WoT[o][d] = fp16(Wo[d][o])

// ============================================================
// Helpers (plain sm_80+ PTX: mma.sync / ldmatrix / cp.async)
// ============================================================
__device__ __forceinline__ uint32_t smem_u32(const void* p) {
    uint32_t a;
    asm("{ .reg .u64 t; cvta.to.shared.u64 t, %1; cvt.u32.u64 %0, t; }"
        : "=r"(a) : "l"(p));
    return a;
}

#define CP_ASYNC_16(dst, src) \
    asm volatile("cp.async.cg.shared.global [%0], [%1], 16;" \
                 :: "r"((uint32_t)(dst)), "l"(src))
#define CP_ASYNC_COMMIT() asm volatile("cp.async.commit_group;" ::: "memory")
#define CP_ASYNC_WAIT0()  asm volatile("cp.async.wait_group 0;" ::: "memory")

__device__ __forceinline__ void ldsm_x4(uint32_t r[4], uint32_t addr) {
    asm volatile("ldmatrix.sync.aligned.m8n8.x4.shared.b16 {%0,%1,%2,%3}, [%4];"
                 : "=r"(r[0]), "=r"(r[1]), "=r"(r[2]), "=r"(r[3]) : "r"(addr));
}

__device__ __forceinline__ void mma_fp16(float c[4], const uint32_t a[4],
                                         const uint32_t b0, const uint32_t b1) {
    asm volatile(
        "mma.sync.aligned.m16n8k16.row.col.f32.f16.f16.f32 "
        "{%0,%1,%2,%3}, {%4,%5,%6,%7}, {%8,%9}, {%0,%1,%2,%3};"
        : "+f"(c[0]), "+f"(c[1]), "+f"(c[2]), "+f"(c[3])
        : "r"(a[0]), "r"(a[1]), "r"(a[2]), "r"(a[3]), "r"(b0), "r"(b1));
}

// ============================================================
// smem layout for big kernel (dynamic)
//   gate row (fp32): 2048 B
//   2 buffers, each: A(128x80=10240) B(256x80=20480) = 30720 B
//   rows: 32 fp16 (64B) data + 16B pad, stride 80 (ldmatrix conflict-free)
// ============================================================
#define ASTRIDE 80
#define OFF_A 0
#define OFF_B 10240
#define BUF_BYTES 30720
#define SMEM_BYTES (2048 + 2 * BUF_BYTES)   // 63488

// ============================================================
// Preamble small GEMM core: BM=64, BN=32, BK=16, 128 threads
// ============================================================
template <int ACT>
__device__ __forceinline__ void gemm_small_body(
    const float* __restrict__ A, const float* __restrict__ W,
    const float* __restrict__ bias, float* __restrict__ C,
    int m0, int n0)
{
    __shared__ float As[16][64];
    __shared__ float Bs[16][32];
    const int t = threadIdx.x;
    const int tx = t & 7, ty = t >> 3;
    float acc[4][4] = {};
    for (int k0 = 0; k0 < DD; k0 += 16) {
        {
            const int m = t >> 1;
            const int kq = (t & 1) * 8;
            float4 v0 = *(const float4*)&A[(size_t)(m0 + m) * DD + k0 + kq];
            float4 v1 = *(const float4*)&A[(size_t)(m0 + m) * DD + k0 + kq + 4];
            As[kq + 0][m] = v0.x; As[kq + 1][m] = v0.y;
            As[kq + 2][m] = v0.z; As[kq + 3][m] = v0.w;
            As[kq + 4][m] = v1.x; As[kq + 5][m] = v1.y;
            As[kq + 6][m] = v1.z; As[kq + 7][m] = v1.w;
        }
        {
            const int k = t >> 3, n = (t & 7) * 4;
            *(float4*)&Bs[k][n] = *(const float4*)&W[(size_t)(k0 + k) * OD + n0 + n];
        }
        __syncthreads();
        #pragma unroll
        for (int k = 0; k < 16; k++) {
            float a[4], b[4];
            *(float4*)a = *(const float4*)&As[k][ty * 4];
            *(float4*)b = *(const float4*)&Bs[k][tx * 4];
            #pragma unroll
            for (int r = 0; r < 4; r++)
                #pragma unroll
                for (int c = 0; c < 4; c++)
                    acc[r][c] += a[r] * b[c];
        }
        __syncthreads();
    }
    #pragma unroll
    for (int r = 0; r < 4; r++) {
        const int m = m0 + ty * 4 + r;
        float4 v; float* vv = (float*)&v;
        #pragma unroll
        for (int c = 0; c < 4; c++) {
            float x = acc[r][c] + __ldg(&bias[n0 + tx * 4 + c]);
            if (ACT == 1) x = fmaxf(x, 0.0f);
            if (ACT == 2) x = 1.0f / (1.0f + __expf(-x));
            vv[c] = x;
        }
        *(float4*)&C[(size_t)m * OD + n0 + tx * 4] = v;
    }
}

template <int ACT>
__global__ void __launch_bounds__(128)
gemm_small_kernel(const float* __restrict__ A, const float* __restrict__ W,
                  const float* __restrict__ bias, float* __restrict__ C)
{
    gemm_small_body<ACT>(A, W, bias, C, blockIdx.y * 64, blockIdx.x * 32);
}

// Fused first stage: z=0 -> h = relu(text@Wa1+ba1); z=1 -> outx = image@Wx+bx
__global__ void __launch_bounds__(128)
pre_fused_kernel(const float* __restrict__ text, const float* __restrict__ image,
                 const float* __restrict__ Wa1, const float* __restrict__ ba1,
                 const float* __restrict__ Wx,  const float* __restrict__ bx,
                 float* __restrict__ h, float* __restrict__ outx)
{
    if (blockIdx.z == 0)
        gemm_small_body<1>(text, Wa1, ba1, h, blockIdx.y * 64, blockIdx.x * 32);
    else
        gemm_small_body<0>(image, Wx, bx, outx, blockIdx.y * 64, blockIdx.x * 32);
}

// ============================================================
// Preamble: row softmax * text
// ============================================================
__global__ void __launch_bounds__(512)
softmax_mul_kernel(const float* __restrict__ logits, const float* __restrict__ text,
                   float* __restrict__ out)
{
    __shared__ float sdata[512];
    const int row = blockIdx.x, t = threadIdx.x;
    const float v = logits[(size_t)row * DD + t];
    sdata[t] = v; __syncthreads();
    for (int s = 256; s > 0; s >>= 1) { if (t < s) sdata[t] = fmaxf(sdata[t], sdata[t + s]); __syncthreads(); }
    const float mx = sdata[0]; __syncthreads();
    const float e = __expf(v - mx);
    sdata[t] = e; __syncthreads();
    for (int s = 256; s > 0; s >>= 1) { if (t < s) sdata[t] += sdata[t + s]; __syncthreads(); }
    out[(size_t)row * DD + t] = e * (1.0f / sdata[0]) * text[(size_t)row * DD + t];
}

// ============================================================
// Preamble: transpose Wo -> fp16:  WoT[o][d] = fp16(Wo[d][o])
// ============================================================
__global__ void __launch_bounds__(256)
transpose_wo_h(const float* __restrict__ Wo, __half* __restrict__ T)
{
    __shared__ float tile[32][33];
    const int bo = blockIdx.x * 32;
    const int bd = blockIdx.y * 32;
    const int x = threadIdx.x, y = threadIdx.y;   // (32, 8)
    #pragma unroll
    for (int r = 0; r < 4; r++)
        tile[y + 8 * r][x] = Wo[(size_t)(bd + y + 8 * r) * OD + bo + x];
    __syncthreads();
    #pragma unroll
    for (int r = 0; r < 4; r++) {
        const int o = bo + y + 8 * r;
        const int d = bd + x;
        T[(size_t)o * DD + d] = __float2half_rn(tile[x][y + 8 * r]);
    }
}

// ============================================================
// Preamble: fp32 -> fp16 convert (outx)
// ============================================================
__global__ void __launch_bounds__(256)
f32_to_f16_kernel(const float* __restrict__ src, __half* __restrict__ dst)
{
    const int idx = (blockIdx.x * 256 + threadIdx.x) * 4;
    const float4 v = *(const float4*)&src[idx];
    __half2 a = __float22half2_rn(make_float2(v.x, v.y));
    __half2 b = __float22half2_rn(make_float2(v.z, v.w));
    *(uint2*)&dst[idx] = make_uint2(*(uint32_t*)&a, *(uint32_t*)&b);
}

__global__ void mul_kernel(const float* __restrict__ a, const float* __restrict__ b,
                           float* __restrict__ c, int n)
{
    int idx = blockIdx.x * blockDim.x + threadIdx.x;
    if (idx < n) c[idx] = a[idx] * b[idx];
}

// ============================================================
// Big einsum via single-pass fp16 HMMA:
//   out[i,j,o] = sum_d gate[i,d]*outx[j,d]*Wo[d,o] + bo[o]
// grid (2 o-tiles, 4 j-tiles, 512 i) = 4096 CTAs, 256 threads (8 warps).
// CTA tile 128(j) x 256(o); warp tile 64x64 (warp_m = wid&1, warp_n = wid>>1).
// 64x64 warp tiles keep smem traffic (~90 B/cyc) under the 128 B/cyc crossbar
// -> MMA-bound. K chunks of 32, double-buffered cp.async B + staged fp16 A.
// ============================================================
__global__ void __launch_bounds__(256, 1)
big_einsum_hmma_kernel(const __half* __restrict__ outxh, const float* __restrict__ gate,
                       const float* __restrict__ bo, float* __restrict__ out)
{
    extern __shared__ char dynsmem[];
    float* gs = (float*)dynsmem;
    const uint32_t sbase = smem_u32(dynsmem) + 2048u;

    const int i  = blockIdx.z;
    const int j0 = blockIdx.y * 128;
    const int o0 = blockIdx.x * 256;
    const int tid  = threadIdx.x;
    const int wid  = tid >> 5;
    const int lane = tid & 31;
    const int warp_m = wid & 1;     // 2 x 64 rows (j)
    const int warp_n = wid >> 1;    // 4 x 64 cols (o)

    // ---- gate row (fp32) -> smem ----
    gs[tid]       = gate[(size_t)i * DD + tid];
    gs[tid + 256] = gate[(size_t)i * DD + tid + 256];

    // ---- A-build indices: row = tid>>1 (0..127), half-row of 16 fp16 ----
    const int arow = tid >> 1;
    const int ach  = (tid & 1) * 16;

    // ---- cp.async B: 256 rows x 64B per chunk (4 x 16B per thread) ----
    auto cpB = [&](int c, int buf) {
        const int c0 = c * 32;
        const uint32_t bdst = sbase + buf * BUF_BYTES + OFF_B;
        #pragma unroll
        for (int q = 0; q < 4; q++) {
            const int g   = tid + q * 256;      // 0..1023
            const int row = g >> 2;             // 0..255
            const int ck  = g & 3;
            const uint32_t dso = (uint32_t)(row * ASTRIDE + ck * 16);
            const __half* src = g_WoT + (size_t)(o0 + row) * DD + c0 + ck * 8;
            CP_ASYNC_16(bdst + dso, src);
        }
        CP_ASYNC_COMMIT();
    };

    // ---- A gmem load (fp16): 16 halfs = 32B per thread via 2 LDG.128 ----
    uint4 av, av2;
    auto loadA = [&](int c) {
        const __half* p = outxh + (size_t)(j0 + arow) * DD + c * 32 + ach;
        av  = __ldg((const uint4*)p);
        av2 = __ldg((const uint4*)(p + 8));
    };

    // ---- A convert: fp16 -> fp32 * gate -> fp16, store 32B ----
    auto storeA = [&](int c, int buf) {
        const int d0 = c * 32 + ach;
        const __half2* xa = (const __half2*)&av;
        const __half2* xb = (const __half2*)&av2;
        uint32_t w[8];
        #pragma unroll
        for (int q = 0; q < 4; q++) {
            float2 xf = __half22float2(xa[q]);
            const float2 gf = *(const float2*)&gs[d0 + q * 2];
            __half2 r = __float22half2_rn(make_float2(xf.x * gf.x, xf.y * gf.y));
            w[q] = *(uint32_t*)&r;
        }
        #pragma unroll
        for (int q = 0; q < 4; q++) {
            float2 xf = __half22float2(xb[q]);
            const float2 gf = *(const float2*)&gs[d0 + 8 + q * 2];
            __half2 r = __float22half2_rn(make_float2(xf.x * gf.x, xf.y * gf.y));
            w[4 + q] = *(uint32_t*)&r;
        }
        const uint32_t ad = sbase + buf * BUF_BYTES + OFF_A + arow * ASTRIDE + ach * 2;
        asm volatile("st.shared.v4.b32 [%0], {%1,%2,%3,%4};"
                     :: "r"(ad), "r"(w[0]), "r"(w[1]), "r"(w[2]), "r"(w[3]));
        asm volatile("st.shared.v4.b32 [%0], {%1,%2,%3,%4};"
                     :: "r"(ad + 16), "r"(w[4]), "r"(w[5]), "r"(w[6]), "r"(w[7]));
    };

    // ---- ldmatrix lane offsets (bytes) ----
    const uint32_t a_lane = (uint32_t)(((lane & 7) + ((lane >> 3) & 1) * 8) * ASTRIDE
                                       + (lane >> 4) * 16);
    const uint32_t b_lane = (uint32_t)(((lane & 7) + (lane >> 4) * 8) * ASTRIDE
                                       + ((lane >> 3) & 1) * 16);
    const uint32_t a_warp = (uint32_t)(warp_m * 64 * ASTRIDE);
    const uint32_t b_warp = (uint32_t)(warp_n * 64 * ASTRIDE);

    float acc[4][8][4] = {};   // [m-tile 16][n-group 8][frag]

    // ---- prologue ----
    loadA(0);
    cpB(0, 0);
    __syncthreads();          // gs visible
    storeA(0, 0);
    CP_ASYNC_WAIT0();
    __syncthreads();          // buffer 0 ready

    // ---- main loop over 16 K-chunks ----
    for (int c = 0; c < 16; c++) {
        const int buf = c & 1;
        if (c < 15) { loadA(c + 1); cpB(c + 1, buf ^ 1); }

        const uint32_t bb = sbase + buf * BUF_BYTES;
        #pragma unroll
        for (int ks = 0; ks < 2; ks++) {
            uint32_t ah[4][4];
            #pragma unroll
            for (int mt = 0; mt < 4; mt++)
                ldsm_x4(ah[mt], bb + OFF_A + a_warp + a_lane + mt * 16 * ASTRIDE + ks * 32);
            #pragma unroll
            for (int g = 0; g < 4; g++) {
                uint32_t bh[4];
                ldsm_x4(bh, bb + OFF_B + b_warp + b_lane + g * 16 * ASTRIDE + ks * 32);
                #pragma unroll
                for (int mt = 0; mt < 4; mt++) {
                    mma_fp16(acc[mt][g * 2],     ah[mt], bh[0], bh[1]);
                    mma_fp16(acc[mt][g * 2 + 1], ah[mt], bh[2], bh[3]);
                }
            }
        }

        if (c < 15) {
            storeA(c + 1, buf ^ 1);
            CP_ASYNC_WAIT0();
            __syncthreads();
        }
    }

    // ---- epilogue: bias + store ----
    const int colb = o0 + warp_n * 64 + (lane & 3) * 2;
    float2 bv[8];
    #pragma unroll
    for (int nj = 0; nj < 8; nj++)
        bv[nj] = __ldg((const float2*)&bo[colb + nj * 8]);

    const int rowb = j0 + warp_m * 64 + (lane >> 2);
    #pragma unroll
    for (int mt = 0; mt < 4; mt++) {
        #pragma unroll
        for (int h = 0; h < 2; h++) {
            const size_t rbase = ((size_t)i * NB + (rowb + mt * 16 + h * 8)) * OD;
            #pragma unroll
            for (int nj = 0; nj < 8; nj++) {
                float2 v;
                v.x = acc[mt][nj][h * 2]     + bv[nj].x;
                v.y = acc[mt][nj][h * 2 + 1] + bv[nj].y;
                *(float2*)&out[rbase + colb + nj * 8] = v;
            }
        }
    }
}

// ============================================================
// kernel_launch
// ============================================================
extern "C" void kernel_launch(void* const* d_in, const int* in_sizes, int n_in,
                              void* d_out, int out_size)
{
    const float* image = (const float*)d_in[0];
    const float* text  = (const float*)d_in[1];
    const float* Wx  = (const float*)d_in[3];
    const float* bx  = (const float*)d_in[4];
    const float* Wy  = (const float*)d_in[5];
    const float* by  = (const float*)d_in[6];
    const float* Wo  = (const float*)d_in[7];
    const float* bo  = (const float*)d_in[8];
    const float* Wa1 = (const float*)d_in[9];
    const float* ba1 = (const float*)d_in[10];
    const float* Wa2 = (const float*)d_in[11];
    const float* ba2 = (const float*)d_in[12];
    float* out = (float*)d_out;

    float *h, *logits, *textw, *outx, *gate, *tmp;
    __half *wot, *outxh;
    cudaGetSymbolAddress((void**)&h,      g_h);
    cudaGetSymbolAddress((void**)&logits, g_logits);
    cudaGetSymbolAddress((void**)&textw,  g_textw);
    cudaGetSymbolAddress((void**)&outx,   g_outx);
    cudaGetSymbolAddress((void**)&gate,   g_gate);
    cudaGetSymbolAddress((void**)&tmp,    g_tmp);
    cudaGetSymbolAddress((void**)&wot,    g_WoT);
    cudaGetSymbolAddress((void**)&outxh,  g_outxh);

    cudaFuncSetAttribute(big_einsum_hmma_kernel,
                         cudaFuncAttributeMaxDynamicSharedMemorySize, SMEM_BYTES);

    const dim3 gsm(OD / 32, NB / 64);   // (16, 8) = 128 CTAs

    // Wo transpose -> fp16
    transpose_wo_h<<<dim3(16, 16), dim3(32, 8)>>>(Wo, wot);
    // Stage 1 fused: h = relu(text@Wa1+ba1)  and  outx = image@Wx+bx
    pre_fused_kernel<<<dim3(OD / 32, NB / 64, 2), 128>>>(text, image, Wa1, ba1, Wx, bx, h, outx);
    // outx -> fp16 copy for the big kernel's A operand
    f32_to_f16_kernel<<<(NB * DD) / (256 * 4), 256>>>(outx, outxh);
    // logits = h@Wa2+ba2
    gemm_small_kernel<0><<<gsm, 128>>>(h, Wa2, ba2, logits);
    // textw = softmax(logits) * text
    softmax_mul_kernel<<<NB, 512>>>(logits, text, textw);
    // gate = sigmoid(textw@Wy+by)
    gemm_small_kernel<2><<<gsm, 128>>>(textw, Wy, by, gate);

    if (out_size == NB * NB * OD) {
        dim3 grid(OD / 256, NB / 128, NB);   // (2, 4, 512)
        big_einsum_hmma_kernel<<<grid, 256, SMEM_BYTES>>>(outxh, gate, bo, out);
    } else {
        mul_kernel<<<(NB * DD + 255) / 256, 256>>>(gate, outx, tmp, NB * DD);
        gemm_small_kernel<0><<<gsm, 128>>>(tmp, Wo, bo, out);
    }
}

// round 9
// speedup vs baseline: 1.4965x; 1.0231x over previous
#include <cuda_runtime.h>
#include <cuda_fp16.h>
#include <cstdint>

#define NB 512   // batch
#define DD 512   // embed dim
#define OD 512   // out dim

// -------- scratch (no cudaMalloc allowed) --------
__device__ float g_h[NB * DD];
__device__ float g_logits[NB * DD];
__device__ float g_textw[NB * DD];
__device__ float g_outx[NB * DD];
__device__ float g_gate[NB * DD];
__device__ float g_tmp[NB * DD];
__device__ __half g_outxh[NB * DD];  // fp16 copy of outx
__device__ __half g_WoT[OD * DD];    // WoT[o][d] = fp16(Wo[d][o])

// ============================================================
// Helpers (plain sm_80+ PTX: mma.sync / ldmatrix / cp.async)
// ============================================================
__device__ __forceinline__ uint32_t smem_u32(const void* p) {
    uint32_t a;
    asm("{ .reg .u64 t; cvta.to.shared.u64 t, %1; cvt.u32.u64 %0, t; }"
        : "=r"(a) : "l"(p));
    return a;
}

#define CP_ASYNC_16(dst, src) \
    asm volatile("cp.async.cg.shared.global [%0], [%1], 16;" \
                 :: "r"((uint32_t)(dst)), "l"(src))
#define CP_ASYNC_COMMIT() asm volatile("cp.async.commit_group;" ::: "memory")
#define CP_ASYNC_WAIT0()  asm volatile("cp.async.wait_group 0;" ::: "memory")

__device__ __forceinline__ void ldsm_x4(uint32_t r[4], uint32_t addr) {
    asm volatile("ldmatrix.sync.aligned.m8n8.x4.shared.b16 {%0,%1,%2,%3}, [%4];"
                 : "=r"(r[0]), "=r"(r[1]), "=r"(r[2]), "=r"(r[3]) : "r"(addr));
}

__device__ __forceinline__ void mma_fp16(float c[4], const uint32_t a[4],
                                         const uint32_t b0, const uint32_t b1) {
    asm volatile(
        "mma.sync.aligned.m16n8k16.row.col.f32.f16.f16.f32 "
        "{%0,%1,%2,%3}, {%4,%5,%6,%7}, {%8,%9}, {%0,%1,%2,%3};"
        : "+f"(c[0]), "+f"(c[1]), "+f"(c[2]), "+f"(c[3])
        : "r"(a[0]), "r"(a[1]), "r"(a[2]), "r"(a[3]), "r"(b0), "r"(b1));
}

// ============================================================
// smem layout for big kernel (dynamic)
//   gate row (fp32): 2048 B
//   K-chunk = 64: rows hold 64 fp16 = 128B data + 16B pad -> stride 144
//   2 buffers, each: A(128x144=18432) B(256x144=36864) = 55296 B
//   (144/4 mod 32 = 4 -> 8-row ldsm footprints cover all 32 banks once)
// ============================================================
#define ASTRIDE 144
#define OFF_A 0
#define OFF_B 18432
#define BUF_BYTES 55296
#define SMEM_BYTES (2048 + 2 * BUF_BYTES)   // 112640 -> 1 CTA/SM

// ============================================================
// Preamble small GEMM core: BM=64, BN=32, BK=16, 128 threads
// ============================================================
template <int ACT>
__device__ __forceinline__ void gemm_small_body(
    const float* __restrict__ A, const float* __restrict__ W,
    const float* __restrict__ bias, float* __restrict__ C,
    int m0, int n0)
{
    __shared__ float As[16][64];
    __shared__ float Bs[16][32];
    const int t = threadIdx.x;
    const int tx = t & 7, ty = t >> 3;
    float acc[4][4] = {};
    for (int k0 = 0; k0 < DD; k0 += 16) {
        {
            const int m = t >> 1;
            const int kq = (t & 1) * 8;
            float4 v0 = *(const float4*)&A[(size_t)(m0 + m) * DD + k0 + kq];
            float4 v1 = *(const float4*)&A[(size_t)(m0 + m) * DD + k0 + kq + 4];
            As[kq + 0][m] = v0.x; As[kq + 1][m] = v0.y;
            As[kq + 2][m] = v0.z; As[kq + 3][m] = v0.w;
            As[kq + 4][m] = v1.x; As[kq + 5][m] = v1.y;
            As[kq + 6][m] = v1.z; As[kq + 7][m] = v1.w;
        }
        {
            const int k = t >> 3, n = (t & 7) * 4;
            *(float4*)&Bs[k][n] = *(const float4*)&W[(size_t)(k0 + k) * OD + n0 + n];
        }
        __syncthreads();
        #pragma unroll
        for (int k = 0; k < 16; k++) {
            float a[4], b[4];
            *(float4*)a = *(const float4*)&As[k][ty * 4];
            *(float4*)b = *(const float4*)&Bs[k][tx * 4];
            #pragma unroll
            for (int r = 0; r < 4; r++)
                #pragma unroll
                for (int c = 0; c < 4; c++)
                    acc[r][c] += a[r] * b[c];
        }
        __syncthreads();
    }
    #pragma unroll
    for (int r = 0; r < 4; r++) {
        const int m = m0 + ty * 4 + r;
        float4 v; float* vv = (float*)&v;
        #pragma unroll
        for (int c = 0; c < 4; c++) {
            float x = acc[r][c] + __ldg(&bias[n0 + tx * 4 + c]);
            if (ACT == 1) x = fmaxf(x, 0.0f);
            if (ACT == 2) x = 1.0f / (1.0f + __expf(-x));
            vv[c] = x;
        }
        *(float4*)&C[(size_t)m * OD + n0 + tx * 4] = v;
    }
}

template <int ACT>
__global__ void __launch_bounds__(128)
gemm_small_kernel(const float* __restrict__ A, const float* __restrict__ W,
                  const float* __restrict__ bias, float* __restrict__ C)
{
    gemm_small_body<ACT>(A, W, bias, C, blockIdx.y * 64, blockIdx.x * 32);
}

// Fused first stage: z=0 -> h = relu(text@Wa1+ba1); z=1 -> outx = image@Wx+bx
__global__ void __launch_bounds__(128)
pre_fused_kernel(const float* __restrict__ text, const float* __restrict__ image,
                 const float* __restrict__ Wa1, const float* __restrict__ ba1,
                 const float* __restrict__ Wx,  const float* __restrict__ bx,
                 float* __restrict__ h, float* __restrict__ outx)
{
    if (blockIdx.z == 0)
        gemm_small_body<1>(text, Wa1, ba1, h, blockIdx.y * 64, blockIdx.x * 32);
    else
        gemm_small_body<0>(image, Wx, bx, outx, blockIdx.y * 64, blockIdx.x * 32);
}

// ============================================================
// Preamble: row softmax * text
// ============================================================
__global__ void __launch_bounds__(512)
softmax_mul_kernel(const float* __restrict__ logits, const float* __restrict__ text,
                   float* __restrict__ out)
{
    __shared__ float sdata[512];
    const int row = blockIdx.x, t = threadIdx.x;
    const float v = logits[(size_t)row * DD + t];
    sdata[t] = v; __syncthreads();
    for (int s = 256; s > 0; s >>= 1) { if (t < s) sdata[t] = fmaxf(sdata[t], sdata[t + s]); __syncthreads(); }
    const float mx = sdata[0]; __syncthreads();
    const float e = __expf(v - mx);
    sdata[t] = e; __syncthreads();
    for (int s = 256; s > 0; s >>= 1) { if (t < s) sdata[t] += sdata[t + s]; __syncthreads(); }
    out[(size_t)row * DD + t] = e * (1.0f / sdata[0]) * text[(size_t)row * DD + t];
}

// ============================================================
// Preamble: transpose Wo -> fp16:  WoT[o][d] = fp16(Wo[d][o])
// ============================================================
__global__ void __launch_bounds__(256)
transpose_wo_h(const float* __restrict__ Wo, __half* __restrict__ T)
{
    __shared__ float tile[32][33];
    const int bo = blockIdx.x * 32;
    const int bd = blockIdx.y * 32;
    const int x = threadIdx.x, y = threadIdx.y;   // (32, 8)
    #pragma unroll
    for (int r = 0; r < 4; r++)
        tile[y + 8 * r][x] = Wo[(size_t)(bd + y + 8 * r) * OD + bo + x];
    __syncthreads();
    #pragma unroll
    for (int r = 0; r < 4; r++) {
        const int o = bo + y + 8 * r;
        const int d = bd + x;
        T[(size_t)o * DD + d] = __float2half_rn(tile[x][y + 8 * r]);
    }
}

// ============================================================
// Preamble: fp32 -> fp16 convert (outx)
// ============================================================
__global__ void __launch_bounds__(256)
f32_to_f16_kernel(const float* __restrict__ src, __half* __restrict__ dst)
{
    const int idx = (blockIdx.x * 256 + threadIdx.x) * 4;
    const float4 v = *(const float4*)&src[idx];
    __half2 a = __float22half2_rn(make_float2(v.x, v.y));
    __half2 b = __float22half2_rn(make_float2(v.z, v.w));
    *(uint2*)&dst[idx] = make_uint2(*(uint32_t*)&a, *(uint32_t*)&b);
}

__global__ void mul_kernel(const float* __restrict__ a, const float* __restrict__ b,
                           float* __restrict__ c, int n)
{
    int idx = blockIdx.x * blockDim.x + threadIdx.x;
    if (idx < n) c[idx] = a[idx] * b[idx];
}

// ============================================================
// Big einsum via single-pass fp16 HMMA, K-chunk 64:
//   out[i,j,o] = sum_d gate[i,d]*outx[j,d]*Wo[d,o] + bo[o]
// grid (2 o-tiles, 4 j-tiles, 512 i) = 4096 CTAs, 256 threads (8 warps).
// CTA tile 128(j) x 256(o); warp tile 64x64. 8 chunks of K=64 (double the
// MMA burst per barrier vs K=32 -> amortizes the ~1.1K-cyc per-chunk tail).
// ============================================================
__global__ void __launch_bounds__(256, 1)
big_einsum_hmma_kernel(const __half* __restrict__ outxh, const float* __restrict__ gate,
                       const float* __restrict__ bo, float* __restrict__ out)
{
    extern __shared__ char dynsmem[];
    float* gs = (float*)dynsmem;
    const uint32_t sbase = smem_u32(dynsmem) + 2048u;

    const int i  = blockIdx.z;
    const int j0 = blockIdx.y * 128;
    const int o0 = blockIdx.x * 256;
    const int tid  = threadIdx.x;
    const int wid  = tid >> 5;
    const int lane = tid & 31;
    const int warp_m = wid & 1;     // 2 x 64 rows (j)
    const int warp_n = wid >> 1;    // 4 x 64 cols (o)

    // ---- gate row (fp32) -> smem ----
    gs[tid]       = gate[(size_t)i * DD + tid];
    gs[tid + 256] = gate[(size_t)i * DD + tid + 256];

    // ---- A-build indices: row = tid>>1 (0..127), half-row of 32 fp16 ----
    const int arow = tid >> 1;
    const int ach  = (tid & 1) * 32;

    // ---- cp.async B: 256 rows x 128B per chunk (8 x 16B per thread) ----
    auto cpB = [&](int c, int buf) {
        const int c0 = c * 64;
        const uint32_t bdst = sbase + buf * BUF_BYTES + OFF_B;
        #pragma unroll
        for (int q = 0; q < 8; q++) {
            const int g   = tid + q * 256;      // 0..2047
            const int row = g >> 3;             // 0..255
            const int ck  = g & 7;              // 16B chunk in 128B row
            const uint32_t dso = (uint32_t)(row * ASTRIDE + ck * 16);
            const __half* src = g_WoT + (size_t)(o0 + row) * DD + c0 + ck * 8;
            CP_ASYNC_16(bdst + dso, src);
        }
        CP_ASYNC_COMMIT();
    };

    // ---- A gmem load (fp16): 32 halfs = 64B per thread via 4 LDG.128 ----
    uint4 av[4];
    auto loadA = [&](int c) {
        const __half* p = outxh + (size_t)(j0 + arow) * DD + c * 64 + ach;
        #pragma unroll
        for (int q = 0; q < 4; q++) av[q] = __ldg((const uint4*)(p + q * 8));
    };

    // ---- A convert: fp16 -> fp32 * gate -> fp16, store 64B ----
    auto storeA = [&](int c, int buf) {
        const int d0 = c * 64 + ach;
        const uint32_t ad = sbase + buf * BUF_BYTES + OFF_A + arow * ASTRIDE + ach * 2;
        #pragma unroll
        for (int h = 0; h < 4; h++) {
            const __half2* xa = (const __half2*)&av[h];
            uint32_t w[4];
            #pragma unroll
            for (int q = 0; q < 4; q++) {
                float2 xf = __half22float2(xa[q]);
                const float2 gf = *(const float2*)&gs[d0 + h * 8 + q * 2];
                __half2 r = __float22half2_rn(make_float2(xf.x * gf.x, xf.y * gf.y));
                w[q] = *(uint32_t*)&r;
            }
            asm volatile("st.shared.v4.b32 [%0], {%1,%2,%3,%4};"
                         :: "r"(ad + h * 16), "r"(w[0]), "r"(w[1]), "r"(w[2]), "r"(w[3]));
        }
    };

    // ---- ldmatrix lane offsets (bytes) ----
    const uint32_t a_lane = (uint32_t)(((lane & 7) + ((lane >> 3) & 1) * 8) * ASTRIDE
                                       + (lane >> 4) * 16);
    const uint32_t b_lane = (uint32_t)(((lane & 7) + (lane >> 4) * 8) * ASTRIDE
                                       + ((lane >> 3) & 1) * 16);
    const uint32_t a_warp = (uint32_t)(warp_m * 64 * ASTRIDE);
    const uint32_t b_warp = (uint32_t)(warp_n * 64 * ASTRIDE);

    float acc[4][8][4] = {};   // [m-tile 16][n-group 8][frag]

    // ---- prologue ----
    loadA(0);
    cpB(0, 0);
    __syncthreads();          // gs visible
    storeA(0, 0);
    CP_ASYNC_WAIT0();
    __syncthreads();          // buffer 0 ready

    // ---- main loop over 8 K-chunks of 64 ----
    for (int c = 0; c < 8; c++) {
        const int buf = c & 1;
        if (c < 7) { loadA(c + 1); cpB(c + 1, buf ^ 1); }

        const uint32_t bb = sbase + buf * BUF_BYTES;
        #pragma unroll
        for (int ks = 0; ks < 4; ks++) {
            uint32_t ah[4][4];
            #pragma unroll
            for (int mt = 0; mt < 4; mt++)
                ldsm_x4(ah[mt], bb + OFF_A + a_warp + a_lane + mt * 16 * ASTRIDE + ks * 32);
            #pragma unroll
            for (int g = 0; g < 4; g++) {
                uint32_t bh[4];
                ldsm_x4(bh, bb + OFF_B + b_warp + b_lane + g * 16 * ASTRIDE + ks * 32);
                #pragma unroll
                for (int mt = 0; mt < 4; mt++) {
                    mma_fp16(acc[mt][g * 2],     ah[mt], bh[0], bh[1]);
                    mma_fp16(acc[mt][g * 2 + 1], ah[mt], bh[2], bh[3]);
                }
            }
        }

        if (c < 7) {
            storeA(c + 1, buf ^ 1);
            CP_ASYNC_WAIT0();
            __syncthreads();
        }
    }

    // ---- epilogue: bias + store ----
    const int colb = o0 + warp_n * 64 + (lane & 3) * 2;
    float2 bv[8];
    #pragma unroll
    for (int nj = 0; nj < 8; nj++)
        bv[nj] = __ldg((const float2*)&bo[colb + nj * 8]);

    const int rowb = j0 + warp_m * 64 + (lane >> 2);
    #pragma unroll
    for (int mt = 0; mt < 4; mt++) {
        #pragma unroll
        for (int h = 0; h < 2; h++) {
            const size_t rbase = ((size_t)i * NB + (rowb + mt * 16 + h * 8)) * OD;
            #pragma unroll
            for (int nj = 0; nj < 8; nj++) {
                float2 v;
                v.x = acc[mt][nj][h * 2]     + bv[nj].x;
                v.y = acc[mt][nj][h * 2 + 1] + bv[nj].y;
                *(float2*)&out[rbase + colb + nj * 8] = v;
            }
        }
    }
}

// ============================================================
// kernel_launch
// ============================================================
extern "C" void kernel_launch(void* const* d_in, const int* in_sizes, int n_in,
                              void* d_out, int out_size)
{
    const float* image = (const float*)d_in[0];
    const float* text  = (const float*)d_in[1];
    const float* Wx  = (const float*)d_in[3];
    const float* bx  = (const float*)d_in[4];
    const float* Wy  = (const float*)d_in[5];
    const float* by  = (const float*)d_in[6];
    const float* Wo  = (const float*)d_in[7];
    const float* bo  = (const float*)d_in[8];
    const float* Wa1 = (const float*)d_in[9];
    const float* ba1 = (const float*)d_in[10];
    const float* Wa2 = (const float*)d_in[11];
    const float* ba2 = (const float*)d_in[12];
    float* out = (float*)d_out;

    float *h, *logits, *textw, *outx, *gate, *tmp;
    __half *wot, *outxh;
    cudaGetSymbolAddress((void**)&h,      g_h);
    cudaGetSymbolAddress((void**)&logits, g_logits);
    cudaGetSymbolAddress((void**)&textw,  g_textw);
    cudaGetSymbolAddress((void**)&outx,   g_outx);
    cudaGetSymbolAddress((void**)&gate,   g_gate);
    cudaGetSymbolAddress((void**)&tmp,    g_tmp);
    cudaGetSymbolAddress((void**)&wot,    g_WoT);
    cudaGetSymbolAddress((void**)&outxh,  g_outxh);

    cudaFuncSetAttribute(big_einsum_hmma_kernel,
                         cudaFuncAttributeMaxDynamicSharedMemorySize, SMEM_BYTES);

    const dim3 gsm(OD / 32, NB / 64);   // (16, 8) = 128 CTAs

    // Wo transpose -> fp16
    transpose_wo_h<<<dim3(16, 16), dim3(32, 8)>>>(Wo, wot);
    // Stage 1 fused: h = relu(text@Wa1+ba1)  and  outx = image@Wx+bx
    pre_fused_kernel<<<dim3(OD / 32, NB / 64, 2), 128>>>(text, image, Wa1, ba1, Wx, bx, h, outx);
    // outx -> fp16 copy for the big kernel's A operand
    f32_to_f16_kernel<<<(NB * DD) / (256 * 4), 256>>>(outx, outxh);
    // logits = h@Wa2+ba2
    gemm_small_kernel<0><<<gsm, 128>>>(h, Wa2, ba2, logits);
    // textw = softmax(logits) * text
    softmax_mul_kernel<<<NB, 512>>>(logits, text, textw);
    // gate = sigmoid(textw@Wy+by)
    gemm_small_kernel<2><<<gsm, 128>>>(textw, Wy, by, gate);

    if (out_size == NB * NB * OD) {
        dim3 grid(OD / 256, NB / 128, NB);   // (2, 4, 512)
        big_einsum_hmma_kernel<<<grid, 256, SMEM_BYTES>>>(outxh, gate, bo, out);
    } else {
        mul_kernel<<<(NB * DD + 255) / 256, 256>>>(gate, outx, tmp, NB * DD);
        gemm_small_kernel<0><<<gsm, 128>>>(tmp, Wo, bo, out);
    }
}

// round 10
// speedup vs baseline: 1.5110x; 1.0097x over previous
#include <cuda_runtime.h>
#include <cuda_fp16.h>
#include <cstdint>

#define NB 512   // batch
#define DD 512   // embed dim
#define OD 512   // out dim

// -------- scratch (no cudaMalloc allowed) --------
__device__ float g_h[NB * DD];
__device__ float g_logits[NB * DD];
__device__ float g_textw[NB * DD];
__device__ float g_outx[NB * DD];
__device__ float g_gate[NB * DD];
__device__ float g_tmp[NB * DD];
__device__ __half g_outxh[NB * DD];  // fp16 copy of outx
__device__ __half g_WoT[OD * DD];    // WoT[o][d] = fp16(Wo[d][o])

// ============================================================
// Helpers (plain sm_80+ PTX: mma.sync / ldmatrix / cp.async)
// ============================================================
__device__ __forceinline__ uint32_t smem_u32(const void* p) {
    uint32_t a;
    asm("{ .reg .u64 t; cvta.to.shared.u64 t, %1; cvt.u32.u64 %0, t; }"
        : "=r"(a) : "l"(p));
    return a;
}

#define CP_ASYNC_16(dst, src) \
    asm volatile("cp.async.cg.shared.global [%0], [%1], 16;" \
                 :: "r"((uint32_t)(dst)), "l"(src))
#define CP_ASYNC_COMMIT() asm volatile("cp.async.commit_group;" ::: "memory")
#define CP_ASYNC_WAIT0()  asm volatile("cp.async.wait_group 0;" ::: "memory")

__device__ __forceinline__ void ldsm_x4(uint32_t r[4], uint32_t addr) {
    asm volatile("ldmatrix.sync.aligned.m8n8.x4.shared.b16 {%0,%1,%2,%3}, [%4];"
                 : "=r"(r[0]), "=r"(r[1]), "=r"(r[2]), "=r"(r[3]) : "r"(addr));
}

__device__ __forceinline__ void mma_fp16(float c[4], const uint32_t a[4],
                                         const uint32_t b0, const uint32_t b1) {
    asm volatile(
        "mma.sync.aligned.m16n8k16.row.col.f32.f16.f16.f32 "
        "{%0,%1,%2,%3}, {%4,%5,%6,%7}, {%8,%9}, {%0,%1,%2,%3};"
        : "+f"(c[0]), "+f"(c[1]), "+f"(c[2]), "+f"(c[3])
        : "r"(a[0]), "r"(a[1]), "r"(a[2]), "r"(a[3]), "r"(b0), "r"(b1));
}

// ============================================================
// smem layout for big kernel (dynamic)
//   gate rows (fp32, 2 i): 4096 B
//   K-chunk = 64: rows hold 64 fp16 = 128B data + 16B pad -> stride 144
//   2 buffers, each: A0(18432) A1(18432) B(128x144=18432) = 55296 B
//   (144/4 mod 32 = 4 -> 8-row ldsm footprints cover all 32 banks once)
// ============================================================
#define ASTRIDE 144
#define OFF_A0 0
#define OFF_A1 18432
#define OFF_B  36864
#define BUF_BYTES 55296
#define SMEM_BYTES (4096 + 2 * BUF_BYTES)   // 114688 -> 1 CTA/SM

// ============================================================
// Preamble small GEMM core: BM=64, BN=32, BK=16, 128 threads
// ============================================================
template <int ACT>
__device__ __forceinline__ void gemm_small_body(
    const float* __restrict__ A, const float* __restrict__ W,
    const float* __restrict__ bias, float* __restrict__ C,
    int m0, int n0)
{
    __shared__ float As[16][64];
    __shared__ float Bs[16][32];
    const int t = threadIdx.x;
    const int tx = t & 7, ty = t >> 3;
    float acc[4][4] = {};
    for (int k0 = 0; k0 < DD; k0 += 16) {
        {
            const int m = t >> 1;
            const int kq = (t & 1) * 8;
            float4 v0 = *(const float4*)&A[(size_t)(m0 + m) * DD + k0 + kq];
            float4 v1 = *(const float4*)&A[(size_t)(m0 + m) * DD + k0 + kq + 4];
            As[kq + 0][m] = v0.x; As[kq + 1][m] = v0.y;
            As[kq + 2][m] = v0.z; As[kq + 3][m] = v0.w;
            As[kq + 4][m] = v1.x; As[kq + 5][m] = v1.y;
            As[kq + 6][m] = v1.z; As[kq + 7][m] = v1.w;
        }
        {
            const int k = t >> 3, n = (t & 7) * 4;
            *(float4*)&Bs[k][n] = *(const float4*)&W[(size_t)(k0 + k) * OD + n0 + n];
        }
        __syncthreads();
        #pragma unroll
        for (int k = 0; k < 16; k++) {
            float a[4], b[4];
            *(float4*)a = *(const float4*)&As[k][ty * 4];
            *(float4*)b = *(const float4*)&Bs[k][tx * 4];
            #pragma unroll
            for (int r = 0; r < 4; r++)
                #pragma unroll
                for (int c = 0; c < 4; c++)
                    acc[r][c] += a[r] * b[c];
        }
        __syncthreads();
    }
    #pragma unroll
    for (int r = 0; r < 4; r++) {
        const int m = m0 + ty * 4 + r;
        float4 v; float* vv = (float*)&v;
        #pragma unroll
        for (int c = 0; c < 4; c++) {
            float x = acc[r][c] + __ldg(&bias[n0 + tx * 4 + c]);
            if (ACT == 1) x = fmaxf(x, 0.0f);
            if (ACT == 2) x = 1.0f / (1.0f + __expf(-x));
            vv[c] = x;
        }
        *(float4*)&C[(size_t)m * OD + n0 + tx * 4] = v;
    }
}

template <int ACT>
__global__ void __launch_bounds__(128)
gemm_small_kernel(const float* __restrict__ A, const float* __restrict__ W,
                  const float* __restrict__ bias, float* __restrict__ C)
{
    gemm_small_body<ACT>(A, W, bias, C, blockIdx.y * 64, blockIdx.x * 32);
}

// Fused first stage: z=0 -> h = relu(text@Wa1+ba1); z=1 -> outx = image@Wx+bx
__global__ void __launch_bounds__(128)
pre_fused_kernel(const float* __restrict__ text, const float* __restrict__ image,
                 const float* __restrict__ Wa1, const float* __restrict__ ba1,
                 const float* __restrict__ Wx,  const float* __restrict__ bx,
                 float* __restrict__ h, float* __restrict__ outx)
{
    if (blockIdx.z == 0)
        gemm_small_body<1>(text, Wa1, ba1, h, blockIdx.y * 64, blockIdx.x * 32);
    else
        gemm_small_body<0>(image, Wx, bx, outx, blockIdx.y * 64, blockIdx.x * 32);
}

// ============================================================
// Preamble: row softmax * text
// ============================================================
__global__ void __launch_bounds__(512)
softmax_mul_kernel(const float* __restrict__ logits, const float* __restrict__ text,
                   float* __restrict__ out)
{
    __shared__ float sdata[512];
    const int row = blockIdx.x, t = threadIdx.x;
    const float v = logits[(size_t)row * DD + t];
    sdata[t] = v; __syncthreads();
    for (int s = 256; s > 0; s >>= 1) { if (t < s) sdata[t] = fmaxf(sdata[t], sdata[t + s]); __syncthreads(); }
    const float mx = sdata[0]; __syncthreads();
    const float e = __expf(v - mx);
    sdata[t] = e; __syncthreads();
    for (int s = 256; s > 0; s >>= 1) { if (t < s) sdata[t] += sdata[t + s]; __syncthreads(); }
    out[(size_t)row * DD + t] = e * (1.0f / sdata[0]) * text[(size_t)row * DD + t];
}

// ============================================================
// Preamble: transpose Wo -> fp16:  WoT[o][d] = fp16(Wo[d][o])
// ============================================================
__global__ void __launch_bounds__(256)
transpose_wo_h(const float* __restrict__ Wo, __half* __restrict__ T)
{
    __shared__ float tile[32][33];
    const int bo = blockIdx.x * 32;
    const int bd = blockIdx.y * 32;
    const int x = threadIdx.x, y = threadIdx.y;   // (32, 8)
    #pragma unroll
    for (int r = 0; r < 4; r++)
        tile[y + 8 * r][x] = Wo[(size_t)(bd + y + 8 * r) * OD + bo + x];
    __syncthreads();
    #pragma unroll
    for (int r = 0; r < 4; r++) {
        const int o = bo + y + 8 * r;
        const int d = bd + x;
        T[(size_t)o * DD + d] = __float2half_rn(tile[x][y + 8 * r]);
    }
}

// ============================================================
// Preamble: fp32 -> fp16 convert (outx)
// ============================================================
__global__ void __launch_bounds__(256)
f32_to_f16_kernel(const float* __restrict__ src, __half* __restrict__ dst)
{
    const int idx = (blockIdx.x * 256 + threadIdx.x) * 4;
    const float4 v = *(const float4*)&src[idx];
    __half2 a = __float22half2_rn(make_float2(v.x, v.y));
    __half2 b = __float22half2_rn(make_float2(v.z, v.w));
    *(uint2*)&dst[idx] = make_uint2(*(uint32_t*)&a, *(uint32_t*)&b);
}

__global__ void mul_kernel(const float* __restrict__ a, const float* __restrict__ b,
                           float* __restrict__ c, int n)
{
    int idx = blockIdx.x * blockDim.x + threadIdx.x;
    if (idx < n) c[idx] = a[idx] * b[idx];
}

// ============================================================
// Big einsum via single-pass fp16 HMMA, 2 i-values per CTA:
//   out[i,j,o] = sum_d gate[i,d]*outx[j,d]*Wo[d,o] + bo[o]
// grid (4 o-tiles, 4 j-tiles, 256 i-pairs) = 4096 CTAs, 256 threads.
// CTA tile 128(j) x 128(o) x 2(i); warp tile 32x64 (4 j-warps x 2 o-warps).
// B (i-invariant) and raw A bytes (i-invariant) loaded ONCE per chunk and
// reused for both i -> MMA per loaded byte doubled vs round 9.
// ============================================================
__global__ void __launch_bounds__(256, 1)
big_einsum_hmma_kernel(const __half* __restrict__ outxh, const float* __restrict__ gate,
                       const float* __restrict__ bo, float* __restrict__ out)
{
    extern __shared__ char dynsmem[];
    float* gs = (float*)dynsmem;   // [0..511]=gate(i0), [512..1023]=gate(i1)
    const uint32_t sbase = smem_u32(dynsmem) + 4096u;

    const int i0 = blockIdx.z * 2;
    const int j0 = blockIdx.y * 128;
    const int o0 = blockIdx.x * 128;
    const int tid  = threadIdx.x;
    const int wid  = tid >> 5;
    const int lane = tid & 31;
    const int warp_m = wid & 3;     // 4 x 32 rows (j)
    const int warp_n = wid >> 2;    // 2 x 64 cols (o)

    // ---- gate rows (fp32) -> smem ----
    gs[tid]        = gate[(size_t)i0 * DD + tid];
    gs[tid + 256]  = gate[(size_t)i0 * DD + tid + 256];
    gs[tid + 512]  = gate[(size_t)(i0 + 1) * DD + tid];
    gs[tid + 768]  = gate[(size_t)(i0 + 1) * DD + tid + 256];

    // ---- A-build indices: row = tid>>1 (0..127), half-row of 32 fp16 ----
    const int arow = tid >> 1;
    const int ach  = (tid & 1) * 32;

    // ---- cp.async B: 128 rows x 128B per chunk (4 x 16B per thread) ----
    auto cpB = [&](int c, int buf) {
        const int c0 = c * 64;
        const uint32_t bdst = sbase + buf * BUF_BYTES + OFF_B;
        #pragma unroll
        for (int q = 0; q < 4; q++) {
            const int g   = tid + q * 256;      // 0..1023
            const int row = g >> 3;             // 0..127
            const int ck  = g & 7;              // 16B chunk in 128B row
            const uint32_t dso = (uint32_t)(row * ASTRIDE + ck * 16);
            const __half* src = g_WoT + (size_t)(o0 + row) * DD + c0 + ck * 8;
            CP_ASYNC_16(bdst + dso, src);
        }
        CP_ASYNC_COMMIT();
    };

    // ---- A gmem load (raw fp16, i-invariant): 32 halfs = 64B per thread ----
    uint4 av[4];
    auto loadA = [&](int c) {
        const __half* p = outxh + (size_t)(j0 + arow) * DD + c * 64 + ach;
        #pragma unroll
        for (int q = 0; q < 4; q++) av[q] = __ldg((const uint4*)(p + q * 8));
    };

    // ---- A convert twice (gate i0 / i1), store into A0 / A1 ----
    auto storeA = [&](int c, int buf) {
        const int d0 = c * 64 + ach;
        #pragma unroll
        for (int iv = 0; iv < 2; iv++) {
            const uint32_t ad = sbase + buf * BUF_BYTES
                              + (iv ? OFF_A1 : OFF_A0) + arow * ASTRIDE + ach * 2;
            const float* gp = gs + iv * 512 + d0;
            #pragma unroll
            for (int h = 0; h < 4; h++) {
                const __half2* xa = (const __half2*)&av[h];
                uint32_t w[4];
                #pragma unroll
                for (int q = 0; q < 4; q++) {
                    float2 xf = __half22float2(xa[q]);
                    const float2 gf = *(const float2*)&gp[h * 8 + q * 2];
                    __half2 r = __float22half2_rn(make_float2(xf.x * gf.x, xf.y * gf.y));
                    w[q] = *(uint32_t*)&r;
                }
                asm volatile("st.shared.v4.b32 [%0], {%1,%2,%3,%4};"
                             :: "r"(ad + h * 16), "r"(w[0]), "r"(w[1]), "r"(w[2]), "r"(w[3]));
            }
        }
    };

    // ---- ldmatrix lane offsets (bytes) ----
    const uint32_t a_lane = (uint32_t)(((lane & 7) + ((lane >> 3) & 1) * 8) * ASTRIDE
                                       + (lane >> 4) * 16);
    const uint32_t b_lane = (uint32_t)(((lane & 7) + (lane >> 4) * 8) * ASTRIDE
                                       + ((lane >> 3) & 1) * 16);
    const uint32_t a_warp = (uint32_t)(warp_m * 32 * ASTRIDE);
    const uint32_t b_warp = (uint32_t)(warp_n * 64 * ASTRIDE);

    float acc0[2][8][4] = {};   // i0: [m-tile 16][n-group 8][frag]
    float acc1[2][8][4] = {};   // i1

    // ---- prologue ----
    loadA(0);
    cpB(0, 0);
    __syncthreads();          // gs visible
    storeA(0, 0);
    CP_ASYNC_WAIT0();
    __syncthreads();          // buffer 0 ready

    // ---- main loop over 8 K-chunks of 64 ----
    for (int c = 0; c < 8; c++) {
        const int buf = c & 1;
        if (c < 7) { loadA(c + 1); cpB(c + 1, buf ^ 1); }

        const uint32_t bb = sbase + buf * BUF_BYTES;
        #pragma unroll
        for (int ks = 0; ks < 4; ks++) {
            uint32_t a0[2][4], a1[2][4];
            #pragma unroll
            for (int mt = 0; mt < 2; mt++) {
                ldsm_x4(a0[mt], bb + OFF_A0 + a_warp + a_lane + mt * 16 * ASTRIDE + ks * 32);
                ldsm_x4(a1[mt], bb + OFF_A1 + a_warp + a_lane + mt * 16 * ASTRIDE + ks * 32);
            }
            #pragma unroll
            for (int g = 0; g < 4; g++) {
                uint32_t bh[4];
                ldsm_x4(bh, bb + OFF_B + b_warp + b_lane + g * 16 * ASTRIDE + ks * 32);
                #pragma unroll
                for (int mt = 0; mt < 2; mt++) {
                    mma_fp16(acc0[mt][g * 2],     a0[mt], bh[0], bh[1]);
                    mma_fp16(acc0[mt][g * 2 + 1], a0[mt], bh[2], bh[3]);
                    mma_fp16(acc1[mt][g * 2],     a1[mt], bh[0], bh[1]);
                    mma_fp16(acc1[mt][g * 2 + 1], a1[mt], bh[2], bh[3]);
                }
            }
        }

        if (c < 7) {
            storeA(c + 1, buf ^ 1);
            CP_ASYNC_WAIT0();
            __syncthreads();
        }
    }

    // ---- epilogue: bias + store (both i) ----
    const int colb = o0 + warp_n * 64 + (lane & 3) * 2;
    float2 bv[8];
    #pragma unroll
    for (int nj = 0; nj < 8; nj++)
        bv[nj] = __ldg((const float2*)&bo[colb + nj * 8]);

    const int rowb = j0 + warp_m * 32 + (lane >> 2);
    #pragma unroll
    for (int iv = 0; iv < 2; iv++) {
        #pragma unroll
        for (int mt = 0; mt < 2; mt++) {
            #pragma unroll
            for (int h = 0; h < 2; h++) {
                const size_t rbase = ((size_t)(i0 + iv) * NB + (rowb + mt * 16 + h * 8)) * OD;
                #pragma unroll
                for (int nj = 0; nj < 8; nj++) {
                    const float* a = iv ? acc1[mt][nj] : acc0[mt][nj];
                    float2 v;
                    v.x = a[h * 2]     + bv[nj].x;
                    v.y = a[h * 2 + 1] + bv[nj].y;
                    *(float2*)&out[rbase + colb + nj * 8] = v;
                }
            }
        }
    }
}

// ============================================================
// kernel_launch
// ============================================================
extern "C" void kernel_launch(void* const* d_in, const int* in_sizes, int n_in,
                              void* d_out, int out_size)
{
    const float* image = (const float*)d_in[0];
    const float* text  = (const float*)d_in[1];
    const float* Wx  = (const float*)d_in[3];
    const float* bx  = (const float*)d_in[4];
    const float* Wy  = (const float*)d_in[5];
    const float* by  = (const float*)d_in[6];
    const float* Wo  = (const float*)d_in[7];
    const float* bo  = (const float*)d_in[8];
    const float* Wa1 = (const float*)d_in[9];
    const float* ba1 = (const float*)d_in[10];
    const float* Wa2 = (const float*)d_in[11];
    const float* ba2 = (const float*)d_in[12];
    float* out = (float*)d_out;

    float *h, *logits, *textw, *outx, *gate, *tmp;
    __half *wot, *outxh;
    cudaGetSymbolAddress((void**)&h,      g_h);
    cudaGetSymbolAddress((void**)&logits, g_logits);
    cudaGetSymbolAddress((void**)&textw,  g_textw);
    cudaGetSymbolAddress((void**)&outx,   g_outx);
    cudaGetSymbolAddress((void**)&gate,   g_gate);
    cudaGetSymbolAddress((void**)&tmp,    g_tmp);
    cudaGetSymbolAddress((void**)&wot,    g_WoT);
    cudaGetSymbolAddress((void**)&outxh,  g_outxh);

    cudaFuncSetAttribute(big_einsum_hmma_kernel,
                         cudaFuncAttributeMaxDynamicSharedMemorySize, SMEM_BYTES);

    const dim3 gsm(OD / 32, NB / 64);   // (16, 8) = 128 CTAs

    // Wo transpose -> fp16
    transpose_wo_h<<<dim3(16, 16), dim3(32, 8)>>>(Wo, wot);
    // Stage 1 fused: h = relu(text@Wa1+ba1)  and  outx = image@Wx+bx
    pre_fused_kernel<<<dim3(OD / 32, NB / 64, 2), 128>>>(text, image, Wa1, ba1, Wx, bx, h, outx);
    // outx -> fp16 copy for the big kernel's A operand
    f32_to_f16_kernel<<<(NB * DD) / (256 * 4), 256>>>(outx, outxh);
    // logits = h@Wa2+ba2
    gemm_small_kernel<0><<<gsm, 128>>>(h, Wa2, ba2, logits);
    // textw = softmax(logits) * text
    softmax_mul_kernel<<<NB, 512>>>(logits, text, textw);
    // gate = sigmoid(textw@Wy+by)
    gemm_small_kernel<2><<<gsm, 128>>>(textw, Wy, by, gate);

    if (out_size == NB * NB * OD) {
        dim3 grid(OD / 128, NB / 128, NB / 2);   // (4, 4, 256)
        big_einsum_hmma_kernel<<<grid, 256, SMEM_BYTES>>>(outxh, gate, bo, out);
    } else {
        mul_kernel<<<(NB * DD + 255) / 256, 256>>>(gate, outx, tmp, NB * DD);
        gemm_small_kernel<0><<<gsm, 128>>>(tmp, Wo, bo, out);
    }
}

// round 11
// speedup vs baseline: 1.5803x; 1.0459x over previous
#include <cuda_runtime.h>
#include <cuda_fp16.h>
#include <cstdint>

#define NB 512   // batch
#define DD 512   // embed dim
#define OD 512   // out dim

// -------- scratch (no cudaMalloc allowed) --------
__device__ float g_h[NB * DD];
__device__ float g_logits[NB * DD];
__device__ float g_textw[NB * DD];
__device__ float g_outx[NB * DD];
__device__ float g_gate[NB * DD];
__device__ float g_tmp[NB * DD];
__device__ __half g_outxh[NB * DD];  // fp16 copy of outx
__device__ __half g_WoT[OD * DD];    // WoT[o][d] = fp16(Wo[d][o])

// ============================================================
// Helpers (plain sm_80+ PTX: mma.sync / ldmatrix / cp.async)
// ============================================================
__device__ __forceinline__ uint32_t smem_u32(const void* p) {
    uint32_t a;
    asm("{ .reg .u64 t; cvta.to.shared.u64 t, %1; cvt.u32.u64 %0, t; }"
        : "=r"(a) : "l"(p));
    return a;
}

#define CP_ASYNC_16(dst, src) \
    asm volatile("cp.async.cg.shared.global [%0], [%1], 16;" \
                 :: "r"((uint32_t)(dst)), "l"(src))
#define CP_ASYNC_COMMIT() asm volatile("cp.async.commit_group;" ::: "memory")
#define CP_ASYNC_WAIT0()  asm volatile("cp.async.wait_group 0;" ::: "memory")

__device__ __forceinline__ void ldsm_x4(uint32_t r[4], uint32_t addr) {
    asm volatile("ldmatrix.sync.aligned.m8n8.x4.shared.b16 {%0,%1,%2,%3}, [%4];"
                 : "=r"(r[0]), "=r"(r[1]), "=r"(r[2]), "=r"(r[3]) : "r"(addr));
}

__device__ __forceinline__ void mma_fp16(float c[4], const uint32_t a[4],
                                         const uint32_t b0, const uint32_t b1) {
    asm volatile(
        "mma.sync.aligned.m16n8k16.row.col.f32.f16.f16.f32 "
        "{%0,%1,%2,%3}, {%4,%5,%6,%7}, {%8,%9}, {%0,%1,%2,%3};"
        : "+f"(c[0]), "+f"(c[1]), "+f"(c[2]), "+f"(c[3])
        : "r"(a[0]), "r"(a[1]), "r"(a[2]), "r"(a[3]), "r"(b0), "r"(b1));
}

// ============================================================
// smem layout for big kernel (dynamic)
//   gate rows (fp32, 2 i): 4096 B
//   K-chunk = 64: rows hold 64 fp16 = 128B data + 16B pad -> stride 144
//   2 buffers, each: A0(18432) A1(18432) B(128x144=18432) = 55296 B
// ============================================================
#define ASTRIDE 144
#define OFF_A0 0
#define OFF_A1 18432
#define OFF_B  36864
#define BUF_BYTES 55296
#define SMEM_BYTES (4096 + 2 * BUF_BYTES)   // 114688 -> 1 CTA/SM

// ============================================================
// Preamble small GEMM core (software-pipelined):
// BM=64, BN=32, BK=16, 128 threads. Next K-tile LDGs issued
// before the FMA block so global latency hides behind compute.
// WRITE_H: also emit fp16 copy of the output (for outxh).
// ============================================================
template <int ACT, bool WRITE_H>
__device__ __forceinline__ void gemm_small_body(
    const float* __restrict__ A, const float* __restrict__ W,
    const float* __restrict__ bias, float* __restrict__ C,
    __half* __restrict__ Ch, int m0, int n0)
{
    __shared__ float As[16][64];
    __shared__ float Bs[16][32];
    const int t = threadIdx.x;
    const int tx = t & 7, ty = t >> 3;
    const int am = t >> 1, akq = (t & 1) * 8;
    const int bk = t >> 3, bn = (t & 7) * 4;

    float4 ra0, ra1, rb;
    auto ldgTiles = [&](int k0) {
        ra0 = __ldg((const float4*)&A[(size_t)(m0 + am) * DD + k0 + akq]);
        ra1 = __ldg((const float4*)&A[(size_t)(m0 + am) * DD + k0 + akq + 4]);
        rb  = __ldg((const float4*)&W[(size_t)(k0 + bk) * OD + n0 + bn]);
    };

    float acc[4][4] = {};
    ldgTiles(0);

    for (int it = 0; it < 32; it++) {
        if (it) __syncthreads();               // consumers of prev tile done
        As[akq + 0][am] = ra0.x; As[akq + 1][am] = ra0.y;
        As[akq + 2][am] = ra0.z; As[akq + 3][am] = ra0.w;
        As[akq + 4][am] = ra1.x; As[akq + 5][am] = ra1.y;
        As[akq + 6][am] = ra1.z; As[akq + 7][am] = ra1.w;
        *(float4*)&Bs[bk][bn] = rb;
        __syncthreads();                       // tile visible
        if (it < 31) ldgTiles((it + 1) * 16);  // prefetch hides behind FMA

        #pragma unroll
        for (int k = 0; k < 16; k++) {
            float a[4], b[4];
            *(float4*)a = *(const float4*)&As[k][ty * 4];
            *(float4*)b = *(const float4*)&Bs[k][tx * 4];
            #pragma unroll
            for (int r = 0; r < 4; r++)
                #pragma unroll
                for (int c = 0; c < 4; c++)
                    acc[r][c] += a[r] * b[c];
        }
    }

    #pragma unroll
    for (int r = 0; r < 4; r++) {
        const int m = m0 + ty * 4 + r;
        float4 v; float* vv = (float*)&v;
        #pragma unroll
        for (int c = 0; c < 4; c++) {
            float x = acc[r][c] + __ldg(&bias[n0 + tx * 4 + c]);
            if (ACT == 1) x = fmaxf(x, 0.0f);
            if (ACT == 2) x = 1.0f / (1.0f + __expf(-x));
            vv[c] = x;
        }
        *(float4*)&C[(size_t)m * OD + n0 + tx * 4] = v;
        if (WRITE_H) {
            __half2 p0 = __float22half2_rn(make_float2(v.x, v.y));
            __half2 p1 = __float22half2_rn(make_float2(v.z, v.w));
            *(uint2*)&Ch[(size_t)m * OD + n0 + tx * 4] =
                make_uint2(*(uint32_t*)&p0, *(uint32_t*)&p1);
        }
    }
}

template <int ACT>
__global__ void __launch_bounds__(128)
gemm_small_kernel(const float* __restrict__ A, const float* __restrict__ W,
                  const float* __restrict__ bias, float* __restrict__ C)
{
    gemm_small_body<ACT, false>(A, W, bias, C, nullptr, blockIdx.y * 64, blockIdx.x * 32);
}

// Fused first stage: z=0 -> h = relu(text@Wa1+ba1)
//                    z=1 -> outx = image@Wx+bx  (+ fp16 copy outxh)
__global__ void __launch_bounds__(128)
pre_fused_kernel(const float* __restrict__ text, const float* __restrict__ image,
                 const float* __restrict__ Wa1, const float* __restrict__ ba1,
                 const float* __restrict__ Wx,  const float* __restrict__ bx,
                 float* __restrict__ h, float* __restrict__ outx,
                 __half* __restrict__ outxh)
{
    if (blockIdx.z == 0)
        gemm_small_body<1, false>(text, Wa1, ba1, h, nullptr, blockIdx.y * 64, blockIdx.x * 32);
    else
        gemm_small_body<0, true>(image, Wx, bx, outx, outxh, blockIdx.y * 64, blockIdx.x * 32);
}

// ============================================================
// Preamble: row softmax * text
// ============================================================
__global__ void __launch_bounds__(512)
softmax_mul_kernel(const float* __restrict__ logits, const float* __restrict__ text,
                   float* __restrict__ out)
{
    __shared__ float sdata[512];
    const int row = blockIdx.x, t = threadIdx.x;
    const float v = logits[(size_t)row * DD + t];
    sdata[t] = v; __syncthreads();
    for (int s = 256; s > 0; s >>= 1) { if (t < s) sdata[t] = fmaxf(sdata[t], sdata[t + s]); __syncthreads(); }
    const float mx = sdata[0]; __syncthreads();
    const float e = __expf(v - mx);
    sdata[t] = e; __syncthreads();
    for (int s = 256; s > 0; s >>= 1) { if (t < s) sdata[t] += sdata[t + s]; __syncthreads(); }
    out[(size_t)row * DD + t] = e * (1.0f / sdata[0]) * text[(size_t)row * DD + t];
}

// ============================================================
// Preamble: transpose Wo -> fp16:  WoT[o][d] = fp16(Wo[d][o])
// ============================================================
__global__ void __launch_bounds__(256)
transpose_wo_h(const float* __restrict__ Wo, __half* __restrict__ T)
{
    __shared__ float tile[32][33];
    const int bo = blockIdx.x * 32;
    const int bd = blockIdx.y * 32;
    const int x = threadIdx.x, y = threadIdx.y;   // (32, 8)
    #pragma unroll
    for (int r = 0; r < 4; r++)
        tile[y + 8 * r][x] = Wo[(size_t)(bd + y + 8 * r) * OD + bo + x];
    __syncthreads();
    #pragma unroll
    for (int r = 0; r < 4; r++) {
        const int o = bo + y + 8 * r;
        const int d = bd + x;
        T[(size_t)o * DD + d] = __float2half_rn(tile[x][y + 8 * r]);
    }
}

__global__ void mul_kernel(const float* __restrict__ a, const float* __restrict__ b,
                           float* __restrict__ c, int n)
{
    int idx = blockIdx.x * blockDim.x + threadIdx.x;
    if (idx < n) c[idx] = a[idx] * b[idx];
}

// ============================================================
// Big einsum via single-pass fp16 HMMA, 2 i-values per CTA
// (unchanged from round 10 — equal-best 627.7us structure):
//   out[i,j,o] = sum_d gate[i,d]*outx[j,d]*Wo[d,o] + bo[o]
// ============================================================
__global__ void __launch_bounds__(256, 1)
big_einsum_hmma_kernel(const __half* __restrict__ outxh, const float* __restrict__ gate,
                       const float* __restrict__ bo, float* __restrict__ out)
{
    extern __shared__ char dynsmem[];
    float* gs = (float*)dynsmem;   // [0..511]=gate(i0), [512..1023]=gate(i1)
    const uint32_t sbase = smem_u32(dynsmem) + 4096u;

    const int i0 = blockIdx.z * 2;
    const int j0 = blockIdx.y * 128;
    const int o0 = blockIdx.x * 128;
    const int tid  = threadIdx.x;
    const int wid  = tid >> 5;
    const int lane = tid & 31;
    const int warp_m = wid & 3;     // 4 x 32 rows (j)
    const int warp_n = wid >> 2;    // 2 x 64 cols (o)

    gs[tid]        = gate[(size_t)i0 * DD + tid];
    gs[tid + 256]  = gate[(size_t)i0 * DD + tid + 256];
    gs[tid + 512]  = gate[(size_t)(i0 + 1) * DD + tid];
    gs[tid + 768]  = gate[(size_t)(i0 + 1) * DD + tid + 256];

    const int arow = tid >> 1;
    const int ach  = (tid & 1) * 32;

    auto cpB = [&](int c, int buf) {
        const int c0 = c * 64;
        const uint32_t bdst = sbase + buf * BUF_BYTES + OFF_B;
        #pragma unroll
        for (int q = 0; q < 4; q++) {
            const int g   = tid + q * 256;
            const int row = g >> 3;
            const int ck  = g & 7;
            const uint32_t dso = (uint32_t)(row * ASTRIDE + ck * 16);
            const __half* src = g_WoT + (size_t)(o0 + row) * DD + c0 + ck * 8;
            CP_ASYNC_16(bdst + dso, src);
        }
        CP_ASYNC_COMMIT();
    };

    uint4 av[4];
    auto loadA = [&](int c) {
        const __half* p = outxh + (size_t)(j0 + arow) * DD + c * 64 + ach;
        #pragma unroll
        for (int q = 0; q < 4; q++) av[q] = __ldg((const uint4*)(p + q * 8));
    };

    auto storeA = [&](int c, int buf) {
        const int d0 = c * 64 + ach;
        #pragma unroll
        for (int iv = 0; iv < 2; iv++) {
            const uint32_t ad = sbase + buf * BUF_BYTES
                              + (iv ? OFF_A1 : OFF_A0) + arow * ASTRIDE + ach * 2;
            const float* gp = gs + iv * 512 + d0;
            #pragma unroll
            for (int h = 0; h < 4; h++) {
                const __half2* xa = (const __half2*)&av[h];
                uint32_t w[4];
                #pragma unroll
                for (int q = 0; q < 4; q++) {
                    float2 xf = __half22float2(xa[q]);
                    const float2 gf = *(const float2*)&gp[h * 8 + q * 2];
                    __half2 r = __float22half2_rn(make_float2(xf.x * gf.x, xf.y * gf.y));
                    w[q] = *(uint32_t*)&r;
                }
                asm volatile("st.shared.v4.b32 [%0], {%1,%2,%3,%4};"
                             :: "r"(ad + h * 16), "r"(w[0]), "r"(w[1]), "r"(w[2]), "r"(w[3]));
            }
        }
    };

    const uint32_t a_lane = (uint32_t)(((lane & 7) + ((lane >> 3) & 1) * 8) * ASTRIDE
                                       + (lane >> 4) * 16);
    const uint32_t b_lane = (uint32_t)(((lane & 7) + (lane >> 4) * 8) * ASTRIDE
                                       + ((lane >> 3) & 1) * 16);
    const uint32_t a_warp = (uint32_t)(warp_m * 32 * ASTRIDE);
    const uint32_t b_warp = (uint32_t)(warp_n * 64 * ASTRIDE);

    float acc0[2][8][4] = {};
    float acc1[2][8][4] = {};

    loadA(0);
    cpB(0, 0);
    __syncthreads();
    storeA(0, 0);
    CP_ASYNC_WAIT0();
    __syncthreads();

    for (int c = 0; c < 8; c++) {
        const int buf = c & 1;
        if (c < 7) { loadA(c + 1); cpB(c + 1, buf ^ 1); }

        const uint32_t bb = sbase + buf * BUF_BYTES;
        #pragma unroll
        for (int ks = 0; ks < 4; ks++) {
            uint32_t a0[2][4], a1[2][4];
            #pragma unroll
            for (int mt = 0; mt < 2; mt++) {
                ldsm_x4(a0[mt], bb + OFF_A0 + a_warp + a_lane + mt * 16 * ASTRIDE + ks * 32);
                ldsm_x4(a1[mt], bb + OFF_A1 + a_warp + a_lane + mt * 16 * ASTRIDE + ks * 32);
            }
            #pragma unroll
            for (int g = 0; g < 4; g++) {
                uint32_t bh[4];
                ldsm_x4(bh, bb + OFF_B + b_warp + b_lane + g * 16 * ASTRIDE + ks * 32);
                #pragma unroll
                for (int mt = 0; mt < 2; mt++) {
                    mma_fp16(acc0[mt][g * 2],     a0[mt], bh[0], bh[1]);
                    mma_fp16(acc0[mt][g * 2 + 1], a0[mt], bh[2], bh[3]);
                    mma_fp16(acc1[mt][g * 2],     a1[mt], bh[0], bh[1]);
                    mma_fp16(acc1[mt][g * 2 + 1], a1[mt], bh[2], bh[3]);
                }
            }
        }

        if (c < 7) {
            storeA(c + 1, buf ^ 1);
            CP_ASYNC_WAIT0();
            __syncthreads();
        }
    }

    const int colb = o0 + warp_n * 64 + (lane & 3) * 2;
    float2 bv[8];
    #pragma unroll
    for (int nj = 0; nj < 8; nj++)
        bv[nj] = __ldg((const float2*)&bo[colb + nj * 8]);

    const int rowb = j0 + warp_m * 32 + (lane >> 2);
    #pragma unroll
    for (int iv = 0; iv < 2; iv++) {
        #pragma unroll
        for (int mt = 0; mt < 2; mt++) {
            #pragma unroll
            for (int h = 0; h < 2; h++) {
                const size_t rbase = ((size_t)(i0 + iv) * NB + (rowb + mt * 16 + h * 8)) * OD;
                #pragma unroll
                for (int nj = 0; nj < 8; nj++) {
                    const float* a = iv ? acc1[mt][nj] : acc0[mt][nj];
                    float2 v;
                    v.x = a[h * 2]     + bv[nj].x;
                    v.y = a[h * 2 + 1] + bv[nj].y;
                    *(float2*)&out[rbase + colb + nj * 8] = v;
                }
            }
        }
    }
}

// ============================================================
// kernel_launch
// ============================================================
extern "C" void kernel_launch(void* const* d_in, const int* in_sizes, int n_in,
                              void* d_out, int out_size)
{
    const float* image = (const float*)d_in[0];
    const float* text  = (const float*)d_in[1];
    const float* Wx  = (const float*)d_in[3];
    const float* bx  = (const float*)d_in[4];
    const float* Wy  = (const float*)d_in[5];
    const float* by  = (const float*)d_in[6];
    const float* Wo  = (const float*)d_in[7];
    const float* bo  = (const float*)d_in[8];
    const float* Wa1 = (const float*)d_in[9];
    const float* ba1 = (const float*)d_in[10];
    const float* Wa2 = (const float*)d_in[11];
    const float* ba2 = (const float*)d_in[12];
    float* out = (float*)d_out;

    float *h, *logits, *textw, *outx, *gate, *tmp;
    __half *wot, *outxh;
    cudaGetSymbolAddress((void**)&h,      g_h);
    cudaGetSymbolAddress((void**)&logits, g_logits);
    cudaGetSymbolAddress((void**)&textw,  g_textw);
    cudaGetSymbolAddress((void**)&outx,   g_outx);
    cudaGetSymbolAddress((void**)&gate,   g_gate);
    cudaGetSymbolAddress((void**)&tmp,    g_tmp);
    cudaGetSymbolAddress((void**)&wot,    g_WoT);
    cudaGetSymbolAddress((void**)&outxh,  g_outxh);

    cudaFuncSetAttribute(big_einsum_hmma_kernel,
                         cudaFuncAttributeMaxDynamicSharedMemorySize, SMEM_BYTES);

    const dim3 gsm(OD / 32, NB / 64);   // (16, 8) = 128 CTAs

    // Wo transpose -> fp16
    transpose_wo_h<<<dim3(16, 16), dim3(32, 8)>>>(Wo, wot);
    // Stage 1 fused: h = relu(text@Wa1+ba1)  and  outx = image@Wx+bx (+ outxh fp16)
    pre_fused_kernel<<<dim3(OD / 32, NB / 64, 2), 128>>>(text, image, Wa1, ba1, Wx, bx,
                                                         h, outx, outxh);
    // logits = h@Wa2+ba2
    gemm_small_kernel<0><<<gsm, 128>>>(h, Wa2, ba2, logits);
    // textw = softmax(logits) * text
    softmax_mul_kernel<<<NB, 512>>>(logits, text, textw);
    // gate = sigmoid(textw@Wy+by)
    gemm_small_kernel<2><<<gsm, 128>>>(textw, Wy, by, gate);

    if (out_size == NB * NB * OD) {
        dim3 grid(OD / 128, NB / 128, NB / 2);   // (4, 4, 256)
        big_einsum_hmma_kernel<<<grid, 256, SMEM_BYTES>>>(outxh, gate, bo, out);
    } else {
        mul_kernel<<<(NB * DD + 255) / 256, 256>>>(gate, outx, tmp, NB * DD);
        gemm_small_kernel<0><<<gsm, 128>>>(tmp, Wo, bo, out);
    }
}